// round 14
// baseline (speedup 1.0000x reference)
#include <cuda_runtime.h>
#include <cuda_bf16.h>
#include <cstdint>

#define DEV __device__ __forceinline__

static constexpr int   THREADS = 768;   // 24 warps (RF-capped sweet spot)
static constexpr float SCALE_Q = 0.223606797749978969f;   // 20^-0.5
static constexpr float LOG2E   = 1.4426950408889634f;
static constexpr float MASKC   = 144.26950408889634f;     // 100 * log2(e)

// ---------------- shared memory layout (bytes) ----------------
static constexpr int LDA  = 136;   // elems; 272B rows -> conflict-free LDSM
static constexpr int LDVT = 200;   // 400B rows
static constexpr int LDX1 = 124;

static constexpr int OFF_X    = 0;                         // sX bf16[192][136] | later proj W
static constexpr int OFF_WB   = OFF_X  + 192 * LDA * 2;    // sW (Wq, later Wv) | alias sO bf16[64][136]
static constexpr int OFF_K    = OFF_WB + 120 * LDA * 2;    // sK bf16[6][192][24]
static constexpr int OFF_VT   = OFF_K  + 6 * 192 * 24 * 2; // Wk staging, then sVt bf16[6][24][200] | alias sX1 f32[64][124]
static constexpr int OFF_Q    = OFF_VT + 6 * 24 * LDVT * 2;// sQ bf16[6][64][24]
static constexpr int OFF_PRED = OFF_Q  + 6 * 64 * 24 * 2;  // f32[64]
static constexpr int OFF_RID  = OFF_PRED + 256;            // int[64]
static constexpr int SMEM_TOTAL = OFF_RID + 256;           // 216704 B

// ---------------- preprocessed device globals ----------------
__device__ __align__(16) __nv_bfloat16 g_wqkv[360 * 128];     // qkv_w padded; q rows pre-scaled by SCALE_Q*log2e
__device__ __align__(16) __nv_bfloat16 g_projw[120 * 128];    // proj_w padded
__device__ __align__(16) float         g_bqkv[360];           // qkv bias; q part pre-scaled by SCALE_Q*log2e
__device__ __align__(16) __nv_bfloat16 g_rpb[6 * 64 * 192];   // gathered rel-pos bias [h][q][k], pre-scaled by log2e

__global__ void prep_kernel(const float* __restrict__ qkv_w, const float* __restrict__ qkv_b,
                            const float* __restrict__ proj_w, const float* __restrict__ rpb_table,
                            const int* __restrict__ rel_idx)
{
    const int i0 = blockIdx.x * blockDim.x + threadIdx.x;
    const int st = gridDim.x * blockDim.x;
    for (int t = i0; t < 360 * 128; t += st) {
        int r = t >> 7, c = t & 127;
        float v = (c < 120) ? qkv_w[r * 120 + c] : 0.f;
        if (r < 120) v *= SCALE_Q * LOG2E;
        g_wqkv[t] = __float2bfloat16(v);
    }
    for (int t = i0; t < 120 * 128; t += st) {
        int r = t >> 7, c = t & 127;
        g_projw[t] = __float2bfloat16((c < 120) ? proj_w[r * 120 + c] : 0.f);
    }
    for (int t = i0; t < 360; t += st)
        g_bqkv[t] = qkv_b[t] * ((t < 120) ? SCALE_Q * LOG2E : 1.f);
    for (int t = i0; t < 6 * 64 * 192; t += st) {
        int h = t / 12288, rem = t % 12288;          // rem = q*192 + k  (rel_idx flat order)
        g_rpb[t] = __float2bfloat16(rpb_table[rel_idx[rem] * 6 + h] * LOG2E);
    }
}

// ---------------- mma / ldmatrix helpers ----------------
DEV uint32_t s2u(const void* p) { return (uint32_t)__cvta_generic_to_shared(p); }

DEV void ldsm4(uint32_t* r, uint32_t a) {
    asm volatile("ldmatrix.sync.aligned.m8n8.x4.shared.b16 {%0,%1,%2,%3}, [%4];"
                 : "=r"(r[0]), "=r"(r[1]), "=r"(r[2]), "=r"(r[3]) : "r"(a));
}
DEV void ldsm2(uint32_t* r, uint32_t a) {
    asm volatile("ldmatrix.sync.aligned.m8n8.x2.shared.b16 {%0,%1}, [%2];"
                 : "=r"(r[0]), "=r"(r[1]) : "r"(a));
}

DEV uint32_t packbf(float a, float b) {
    __nv_bfloat162 t = __floats2bfloat162_rn(a, b);
    return *reinterpret_cast<uint32_t*>(&t);
}

DEV float ex2(float x) {
    float y;
    asm("ex2.approx.f32 %0, %1;" : "=f"(y) : "f"(x));
    return y;
}

DEV void mma16816(float* c, uint32_t a0, uint32_t a1, uint32_t a2, uint32_t a3,
                  uint32_t b0, uint32_t b1) {
    asm volatile("mma.sync.aligned.m16n8k16.row.col.f32.bf16.bf16.f32 "
                 "{%0,%1,%2,%3}, {%4,%5,%6,%7}, {%8,%9}, {%0,%1,%2,%3};\n"
                 : "+f"(c[0]), "+f"(c[1]), "+f"(c[2]), "+f"(c[3])
                 : "r"(a0), "r"(a1), "r"(a2), "r"(a3), "r"(b0), "r"(b1));
}

DEV void mma1688(float* c, uint32_t a0, uint32_t a1, uint32_t b0) {
    asm volatile("mma.sync.aligned.m16n8k8.row.col.f32.bf16.bf16.f32 "
                 "{%0,%1,%2,%3}, {%4,%5}, {%6}, {%0,%1,%2,%3};\n"
                 : "+f"(c[0]), "+f"(c[1]), "+f"(c[2]), "+f"(c[3])
                 : "r"(a0), "r"(a1), "r"(b0));
}

// 16(M) x 40(N) x 128(K): A row-major [.,LDA], B n-major [n][k] stride LDA. LDSM-fed.
DEV void gemm16x40(const __nv_bfloat16* __restrict__ A, const __nv_bfloat16* __restrict__ B,
                   float* acc, int lane)
{
    const int r16 = lane & 15, k8 = (lane >> 4) * 8;
    uint32_t aA  = s2u(A + r16 * LDA + k8);
    uint32_t aB0 = s2u(B + r16 * LDA + k8);
    uint32_t aB1 = s2u(B + (16 + r16) * LDA + k8);
    uint32_t aB2 = s2u(B + (32 + (lane & 7)) * LDA + ((lane >> 3) & 1) * 8);
#pragma unroll
    for (int ks = 0; ks < 8; ks++) {
        uint32_t av[4], b0[4], b1[4], b2[2];
        ldsm4(av, aA); ldsm4(b0, aB0); ldsm4(b1, aB1); ldsm2(b2, aB2);
        aA += 32; aB0 += 32; aB1 += 32; aB2 += 32;
        mma16816(acc + 0,  av[0], av[1], av[2], av[3], b0[0], b0[2]);
        mma16816(acc + 4,  av[0], av[1], av[2], av[3], b0[1], b0[3]);
        mma16816(acc + 8,  av[0], av[1], av[2], av[3], b1[0], b1[2]);
        mma16816(acc + 12, av[0], av[1], av[2], av[3], b1[1], b1[3]);
        mma16816(acc + 16, av[0], av[1], av[2], av[3], b2[0], b2[1]);
    }
}

// 32(M) x 40(N) x 128(K). acc[s*8+0..3] = rows 0-15 of tile s, +4..7 = rows 16-31.
DEV void gemm32x40(const __nv_bfloat16* __restrict__ A, const __nv_bfloat16* __restrict__ B,
                   float* acc, int lane)
{
    const int r16 = lane & 15, k8 = (lane >> 4) * 8;
    uint32_t aA0 = s2u(A + r16 * LDA + k8);
    uint32_t aA1 = s2u(A + (16 + r16) * LDA + k8);
    uint32_t aB0 = s2u(B + r16 * LDA + k8);
    uint32_t aB1 = s2u(B + (16 + r16) * LDA + k8);
    uint32_t aB2 = s2u(B + (32 + (lane & 7)) * LDA + ((lane >> 3) & 1) * 8);
#pragma unroll
    for (int ks = 0; ks < 8; ks++) {
        uint32_t av0[4], av1[4], b0[4], b1[4], b2[2];
        ldsm4(av0, aA0); ldsm4(av1, aA1); ldsm4(b0, aB0); ldsm4(b1, aB1); ldsm2(b2, aB2);
        aA0 += 32; aA1 += 32; aB0 += 32; aB1 += 32; aB2 += 32;
        mma16816(acc + 0,  av0[0], av0[1], av0[2], av0[3], b0[0], b0[2]);
        mma16816(acc + 4,  av1[0], av1[1], av1[2], av1[3], b0[0], b0[2]);
        mma16816(acc + 8,  av0[0], av0[1], av0[2], av0[3], b0[1], b0[3]);
        mma16816(acc + 12, av1[0], av1[1], av1[2], av1[3], b0[1], b0[3]);
        mma16816(acc + 16, av0[0], av0[1], av0[2], av0[3], b1[0], b1[2]);
        mma16816(acc + 20, av1[0], av1[1], av1[2], av1[3], b1[0], b1[2]);
        mma16816(acc + 24, av0[0], av0[1], av0[2], av0[3], b1[1], b1[3]);
        mma16816(acc + 28, av1[0], av1[1], av1[2], av1[3], b1[1], b1[3]);
        mma16816(acc + 32, av0[0], av0[1], av0[2], av0[3], b2[0], b2[1]);
        mma16816(acc + 36, av1[0], av1[1], av1[2], av1[3], b2[0], b2[1]);
    }
}

DEV void stage_w(const __nv_bfloat16* __restrict__ gsrc, __nv_bfloat16* __restrict__ sdst, int tid) {
    for (int i = tid; i < 120 * 16; i += THREADS) {
        int r = i >> 4, c = i & 15;
        *reinterpret_cast<uint4*>(sdst + r * LDA + c * 8) =
            *reinterpret_cast<const uint4*>(gsrc + r * 128 + c * 8);
    }
}

// ---------------- main fused kernel: one CTA per window ----------------
__global__ void __launch_bounds__(THREADS, 1)
swin_main_kernel(const float* __restrict__ x, const float* __restrict__ quary0,
                 const float* __restrict__ quary1, const float* __restrict__ proj_b,
                 const float* __restrict__ pm_w, const float* __restrict__ pm_b,
                 float* __restrict__ out)
{
    extern __shared__ char smem[];
    __nv_bfloat16* sX   = (__nv_bfloat16*)(smem + OFF_X);
    __nv_bfloat16* sWp  = (__nv_bfloat16*)(smem + OFF_X);    // proj W (aliases sX, staged after G2)
    __nv_bfloat16* sW   = (__nv_bfloat16*)(smem + OFF_WB);   // Wq, then Wv
    __nv_bfloat16* sO   = (__nv_bfloat16*)(smem + OFF_WB);   // attention output (alias)
    __nv_bfloat16* sK   = (__nv_bfloat16*)(smem + OFF_K);
    __nv_bfloat16* sWk  = (__nv_bfloat16*)(smem + OFF_VT);   // K weights staged (alias)
    __nv_bfloat16* sVt  = (__nv_bfloat16*)(smem + OFF_VT);
    float*         sX1  = (float*)(smem + OFF_VT);
    __nv_bfloat16* sQ   = (__nv_bfloat16*)(smem + OFF_Q);
    float*         sPred= (float*)(smem + OFF_PRED);
    int*           sRid = (int*)(smem + OFF_RID);

    const int tid  = threadIdx.x;
    const int lane = tid & 31;
    const int warp = tid >> 5;          // 0..23
    const int grp  = lane >> 2;         // 0..7
    const int tg   = lane & 3;          // 0..3
    const int wi   = blockIdx.x;
    const int wy   = wi >> 5, wx = wi & 31;
    const bool maskw = (wy == 31) || (wx == 31);
    const __nv_bfloat16 bz   = __float2bfloat16(0.f);
    const __nv_bfloat16 bone = __float2bfloat16(1.f);

    // =========== Phase A: window load, pads, region ids, Wq+Wk stage ===========
    for (int i = tid; i < 192 * 30; i += THREADS) {
        int n = i / 30, v = i - n * 30;
        int f = n >> 6, p = n & 63;
        int rowg = (wy * 8 + (p >> 3) + 4) & 255;
        int colg = (wx * 8 + (p & 7) + 4) & 255;
        float4 t = *reinterpret_cast<const float4*>(
            x + ((size_t)((f * 256 + rowg) * 256 + colg)) * 120 + v * 4);
        uint32_t* dst = reinterpret_cast<uint32_t*>(sX + n * LDA + v * 4);
        dst[0] = packbf(t.x, t.y);
        dst[1] = packbf(t.z, t.w);
    }
    for (int i = tid; i < 192 * 8; i += THREADS) sX[(i >> 3) * LDA + 120 + (i & 7)] = bz;
    for (int i = tid; i < 6 * 64 * 4; i += THREADS) {
        int h = i >> 8, r = (i >> 2) & 63, c = 20 + (i & 3);
        sQ[(h * 64 + r) * 24 + c] = bz;
    }
    for (int i = tid; i < 6 * 192 * 4; i += THREADS) {
        int h = i / 768, r = (i >> 2) % 192, c = 20 + (i & 3);
        sK[(h * 192 + r) * 24 + c] = bz;
    }
    if (tid < 64) {
        int r = tid >> 3, c = tid & 7;
        int rz = (wy == 31) ? ((r < 4) ? 1 : 2) : 0;
        int cz = (wx == 31) ? ((c < 4) ? 1 : 2) : 0;
        sRid[tid] = rz * 3 + cz;
    }
    stage_w(g_wqkv,             sW,  tid);   // Wq (pre-scaled incl. log2e)
    stage_w(g_wqkv + 120 * 128, sWk, tid);   // Wk -> staged in (future) sVt region
    __syncthreads();

    // =========== G1: K GEMM (warps 0..17, 32x40) + Q GEMM (warps 18..23, 32x40) ===========
    if (warp < 18) {
        const int r = warp / 3, nt = warp % 3;
        float acc[40];
#pragma unroll
        for (int i = 0; i < 40; i++) acc[i] = 0.f;
        gemm32x40(sX + r * 32 * LDA, sWk + (nt * 40) * LDA, acc, lane);
        const int t0 = r * 32 + grp;
#pragma unroll
        for (int s = 0; s < 5; s++) {
            int oc = nt * 40 + s * 8 + tg * 2;
            int hh = oc / 20, d = oc % 20;
            float b0 = g_bqkv[120 + oc], b1 = g_bqkv[121 + oc];
            __nv_bfloat16* base = sK + (hh * 192) * 24 + d;
            *reinterpret_cast<uint32_t*>(base + (t0     ) * 24) = packbf(acc[s*8+0]+b0, acc[s*8+1]+b1);
            *reinterpret_cast<uint32_t*>(base + (t0 +  8) * 24) = packbf(acc[s*8+2]+b0, acc[s*8+3]+b1);
            *reinterpret_cast<uint32_t*>(base + (t0 + 16) * 24) = packbf(acc[s*8+4]+b0, acc[s*8+5]+b1);
            *reinterpret_cast<uint32_t*>(base + (t0 + 24) * 24) = packbf(acc[s*8+6]+b0, acc[s*8+7]+b1);
        }
    } else {
        const int t = warp - 18;                  // 0..5
        const int mblk = t / 3, nt = t % 3;       // mblk: 0..1 (rows 128-159 / 160-191)
        float acc[40];
#pragma unroll
        for (int i = 0; i < 40; i++) acc[i] = 0.f;
        gemm32x40(sX + (128 + mblk * 32) * LDA, sW + (nt * 40) * LDA, acc, lane);
        const int q0 = mblk * 32 + grp;
#pragma unroll
        for (int s = 0; s < 5; s++) {
            int oc = nt * 40 + s * 8 + tg * 2;
            int hh = oc / 20, d = oc % 20;
            float b0 = g_bqkv[oc], b1 = g_bqkv[oc + 1];
            __nv_bfloat16* base = sQ + (hh * 64) * 24 + d;
            *reinterpret_cast<uint32_t*>(base + (q0     ) * 24) = packbf(acc[s*8+0]+b0, acc[s*8+1]+b1);
            *reinterpret_cast<uint32_t*>(base + (q0 +  8) * 24) = packbf(acc[s*8+2]+b0, acc[s*8+3]+b1);
            *reinterpret_cast<uint32_t*>(base + (q0 + 16) * 24) = packbf(acc[s*8+4]+b0, acc[s*8+5]+b1);
            *reinterpret_cast<uint32_t*>(base + (q0 + 24) * 24) = packbf(acc[s*8+6]+b0, acc[s*8+7]+b1);
        }
    }
    __syncthreads();

    // =========== stage Wv (over Wq) + sVt pads: d==20 gets 1.0 (ones column -> row sums) ===========
    stage_w(g_wqkv + 240 * 128, sW, tid);
    for (int i = tid; i < 6 * 4 * 192; i += THREADS) {
        int h = i / 768, rem = i % 768;
        int d = 20 + rem / 192, k = rem % 192;
        sVt[(h * 24 + d) * LDVT + k] = (d == 20) ? bone : bz;
    }
    __syncthreads();

    // =========== G2: V GEMM (warps 0..17, 32x40) + pred (warps 18..23) ===========
    if (warp < 18) {
        const int r = warp / 3, nt = warp % 3;
        float acc[40];
#pragma unroll
        for (int i = 0; i < 40; i++) acc[i] = 0.f;
        gemm32x40(sX + r * 32 * LDA, sW + (nt * 40) * LDA, acc, lane);
        const int t0 = r * 32 + grp;
#pragma unroll
        for (int s = 0; s < 5; s++) {
            int oc = nt * 40 + s * 8 + tg * 2;
            int hh = oc / 20, d = oc % 20;
            float b0 = g_bqkv[240 + oc], b1 = g_bqkv[241 + oc];
            __nv_bfloat16* r0 = sVt + (hh * 24 + d) * LDVT;
            __nv_bfloat16* r1 = sVt + (hh * 24 + d + 1) * LDVT;
            r0[t0     ] = __float2bfloat16(acc[s*8+0] + b0);
            r1[t0     ] = __float2bfloat16(acc[s*8+1] + b1);
            r0[t0 +  8] = __float2bfloat16(acc[s*8+2] + b0);
            r1[t0 +  8] = __float2bfloat16(acc[s*8+3] + b1);
            r0[t0 + 16] = __float2bfloat16(acc[s*8+4] + b0);
            r1[t0 + 16] = __float2bfloat16(acc[s*8+5] + b1);
            r0[t0 + 24] = __float2bfloat16(acc[s*8+6] + b0);
            r1[t0 + 24] = __float2bfloat16(acc[s*8+7] + b1);
        }
    } else {
        // pred (pure fp32 from global x) on the 6 otherwise-idle warps
        const float pmb = pm_b[0];
        for (int it = 0; it < 11; it++) {
            int q = it * 6 + (warp - 18);
            if (q < 64) {
                int rowg = (wy * 8 + (q >> 3) + 4) & 255;
                int colg = (wx * 8 + (q & 7) + 4) & 255;
                const float* xr = x + ((size_t)((2 * 256 + rowg) * 256 + colg)) * 120;
                const float* qr = quary0 + (size_t)(wi * 64 + q) * 120;
                float s = 0.f;
                for (int ch = lane; ch < 120; ch += 32)
                    s += fabsf(xr[ch] - qr[ch]) * pm_w[ch];
#pragma unroll
                for (int off = 16; off; off >>= 1) s += __shfl_xor_sync(0xffffffffu, s, off);
                if (lane == 0) sPred[q] = (s + pmb >= 0.f) ? 1.f : 0.f;
            }
        }
    }
    __syncthreads();

    // sX dead: stage proj W (LDG hides under attention); zero sO pads
    stage_w(g_projw, sWp, tid);
    for (int i = tid; i < 64 * 16; i += THREADS) sO[(i >> 4) * LDA + 120 + (i & 15)] = bz;

    // =========== attention: 24 warp-tasks, 4x48 key chunks, no-max softmax (log2 domain) ===========
    {
        const int h    = warp >> 2;          // 0..5
        const int mblk = warp & 3;           // 0..3
        const int q0   = mblk * 16 + grp;
        const int q1   = q0 + 8;

        uint32_t aq[6];
        {
            const __nv_bfloat16* Qb = sQ + (h * 64 + mblk * 16) * 24;
            ldsm4(aq,     s2u(Qb + (lane & 15) * 24 + (lane >> 4) * 8));
            ldsm2(aq + 4, s2u(Qb + (lane & 15) * 24 + 16));
        }

        float O[12];
#pragma unroll
        for (int i = 0; i < 12; i++) O[i] = 0.f;
        const int rq0 = sRid[q0], rq1 = sRid[q1];

#pragma unroll 1
        for (int c = 0; c < 4; c++) {
            uint32_t ru0[6], ru1[6];
            {
                const uint32_t* rp0 = reinterpret_cast<const uint32_t*>(g_rpb + (h * 64 + q0) * 192 + c * 48) + tg;
                const uint32_t* rp1 = reinterpret_cast<const uint32_t*>(g_rpb + (h * 64 + q1) * 192 + c * 48) + tg;
#pragma unroll
                for (int j = 0; j < 6; j++) { ru0[j] = rp0[j * 4]; ru1[j] = rp1[j * 4]; }
            }

            float s[24];
#pragma unroll
            for (int i = 0; i < 24; i++) s[i] = 0.f;

            const __nv_bfloat16* Kh = sK + (h * 192 + c * 48) * 24;
            {
                uint32_t bp = s2u(Kh + (lane & 15) * 24 + (lane >> 4) * 8);
#pragma unroll
                for (int p = 0; p < 3; p++) {
                    uint32_t kb[4];
                    ldsm4(kb, bp + p * 768);          // 16 tokens * 48B
                    mma16816(s + (2*p  ) * 4, aq[0], aq[1], aq[2], aq[3], kb[0], kb[2]);
                    mma16816(s + (2*p+1) * 4, aq[0], aq[1], aq[2], aq[3], kb[1], kb[3]);
                }
                uint32_t kt[6];
                ldsm4(kt,     s2u(Kh + lane * 24 + 16));
                ldsm2(kt + 4, s2u(Kh + (32 + (lane & 15)) * 24 + 16));
#pragma unroll
                for (int j = 0; j < 6; j++) mma1688(s + j * 4, aq[4], aq[5], kt[j]);
            }

#pragma unroll
            for (int j = 0; j < 6; j++) {
                float2 f0 = __bfloat1622float2(*reinterpret_cast<__nv_bfloat162*>(&ru0[j]));
                float2 f1 = __bfloat1622float2(*reinterpret_cast<__nv_bfloat162*>(&ru1[j]));
                s[j*4+0] += f0.x; s[j*4+1] += f0.y;
                s[j*4+2] += f1.x; s[j*4+3] += f1.y;
            }

            if (maskw) {
#pragma unroll
                for (int j = 0; j < 6; j++) {
                    int kc = (c * 48 + j * 8 + tg * 2) & 63;
                    int rk0 = sRid[kc], rk1 = sRid[kc + 1];
                    if (rk0 != rq0) s[j*4+0] -= MASKC;
                    if (rk1 != rq0) s[j*4+1] -= MASKC;
                    if (rk0 != rq1) s[j*4+2] -= MASKC;
                    if (rk1 != rq1) s[j*4+3] -= MASKC;
                }
            }

#pragma unroll
            for (int i = 0; i < 24; i++) s[i] = ex2(s[i]);

            const __nv_bfloat16* Vh = sVt + (h * 24) * LDVT + c * 48;
            uint32_t pv4 = s2u(Vh + (lane & 15) * LDVT + (lane >> 4) * 8);
            uint32_t pv2 = s2u(Vh + (16 + (lane & 7)) * LDVT + ((lane >> 3) & 1) * 8);
#pragma unroll
            for (int kk = 0; kk < 3; kk++) {
                uint32_t vb[6];
                ldsm4(vb,     pv4 + kk * 32);
                ldsm2(vb + 4, pv2 + kk * 32);
                uint32_t a0 = packbf(s[kk*8+0], s[kk*8+1]);
                uint32_t a1 = packbf(s[kk*8+2], s[kk*8+3]);
                uint32_t a2 = packbf(s[kk*8+4], s[kk*8+5]);
                uint32_t a3 = packbf(s[kk*8+6], s[kk*8+7]);
                mma16816(O + 0, a0, a1, a2, a3, vb[0], vb[2]);
                mma16816(O + 4, a0, a1, a2, a3, vb[1], vb[3]);
                mma16816(O + 8, a0, a1, a2, a3, vb[4], vb[5]);
            }
        }

        // row sums live in col 20 = O[8] (q0) / O[10] (q1) of lanes with tg==2
        const int src = (lane & ~3) | 2;
        const float inv0 = 1.f / __shfl_sync(0xffffffffu, O[8],  src);
        const float inv1 = 1.f / __shfl_sync(0xffffffffu, O[10], src);
#pragma unroll
        for (int nt = 0; nt < 3; nt++) {
            int d = nt * 8 + tg * 2;
            if (d < 20) {
                *reinterpret_cast<uint32_t*>(sO + q0 * LDA + h * 20 + d) = packbf(O[nt*4+0]*inv0, O[nt*4+1]*inv0);
                *reinterpret_cast<uint32_t*>(sO + q1 * LDA + h * 20 + d) = packbf(O[nt*4+2]*inv1, O[nt*4+3]*inv1);
            }
        }
    }
    __syncthreads();

    // =========== proj GEMM + blend (proj W staged in sWp during attention) ===========
    if (warp < 12) {
        const int mt = warp & 3, nt = warp >> 2;
        const int q0 = mt * 16 + grp, q1 = q0 + 8;
        float acc[20];
#pragma unroll
        for (int i = 0; i < 20; i++) acc[i] = 0.f;
        gemm16x40(sO + mt * 16 * LDA, sWp + (nt * 40) * LDA, acc, lane);
#pragma unroll
        for (int s = 0; s < 5; s++) {
            int oc = nt * 40 + s * 8 + tg * 2;
            float b0 = proj_b[oc], b1 = proj_b[oc + 1];
            *reinterpret_cast<float2*>(sX1 + q0 * LDX1 + oc) = make_float2(acc[s*4+0]+b0, acc[s*4+1]+b1);
            *reinterpret_cast<float2*>(sX1 + q1 * LDX1 + oc) = make_float2(acc[s*4+2]+b0, acc[s*4+3]+b1);
        }
    }
    __syncthreads();

    // =========== scatter store: token p -> out[(wy*8+r+4)&255][(wx*8+c+4)&255][121] ===========
    for (int idx = tid; idx < 64 * 121; idx += THREADS) {
        int p = idx / 121, c = idx - p * 121;
        int rowg = (wy * 8 + (p >> 3) + 4) & 255;
        int colg = (wx * 8 + (p & 7) + 4) & 255;
        float pv = sPred[p];
        float v;
        if (c == 120) v = pv;
        else v = (pv != 0.f) ? sX1[p * LDX1 + c] : quary1[(size_t)(wi * 64 + p) * 120 + c];
        out[(size_t)(rowg * 256 + colg) * 121 + c] = v;
    }
}

// ---------------- launch ----------------
extern "C" void kernel_launch(void* const* d_in, const int* in_sizes, int n_in,
                              void* d_out, int out_size)
{
    (void)in_sizes; (void)n_in; (void)out_size;
    const float* x        = (const float*)d_in[0];
    const float* quary0   = (const float*)d_in[1];
    const float* quary1   = (const float*)d_in[2];
    const float* qkv_w    = (const float*)d_in[3];
    const float* qkv_b    = (const float*)d_in[4];
    const float* proj_w   = (const float*)d_in[5];
    const float* proj_b   = (const float*)d_in[6];
    const float* rpb_tab  = (const float*)d_in[7];
    const float* pm_w     = (const float*)d_in[8];
    const float* pm_b     = (const float*)d_in[9];
    // d_in[10] = attn_mask : intentionally unused (recomputed analytically)
    const int*   rel_idx  = (const int*)d_in[11];
    float* out = (float*)d_out;

    cudaFuncSetAttribute(swin_main_kernel, cudaFuncAttributeMaxDynamicSharedMemorySize, SMEM_TOTAL);

    prep_kernel<<<128, 256>>>(qkv_w, qkv_b, proj_w, rpb_tab, rel_idx);
    swin_main_kernel<<<1024, THREADS, SMEM_TOTAL>>>(x, quary0, quary1, proj_b, pm_w, pm_b, out);
}

// round 15
// speedup vs baseline: 1.6425x; 1.6425x over previous
#include <cuda_runtime.h>
#include <cuda_bf16.h>
#include <cstdint>

#define DEV __device__ __forceinline__

static constexpr int   THREADS = 768;   // 24 warps (RF-capped sweet spot)
static constexpr float SCALE_Q = 0.223606797749978969f;   // 20^-0.5
static constexpr float LOG2E   = 1.4426950408889634f;
static constexpr float MASKC   = 144.26950408889634f;     // 100 * log2(e)

// ---------------- shared memory layout (bytes) ----------------
static constexpr int LDA  = 136;   // elems; 272B rows -> conflict-free LDSM
static constexpr int LDVT = 200;   // 400B rows
static constexpr int LDX1 = 124;

static constexpr int OFF_X    = 0;                         // sX bf16[192][136] | later proj W
static constexpr int OFF_WB   = OFF_X  + 192 * LDA * 2;    // sW (Wq, later Wv) | alias sO bf16[64][136]
static constexpr int OFF_K    = OFF_WB + 120 * LDA * 2;    // sK bf16[6][192][24]
static constexpr int OFF_VT   = OFF_K  + 6 * 192 * 24 * 2; // Wk staging, then sVt bf16[6][24][200] | alias sX1 f32[64][124]
static constexpr int OFF_Q    = OFF_VT + 6 * 24 * LDVT * 2;// sQ bf16[6][64][24]
static constexpr int OFF_PRED = OFF_Q  + 6 * 64 * 24 * 2;  // f32[64]
static constexpr int OFF_RID  = OFF_PRED + 256;            // int[64]
static constexpr int SMEM_TOTAL = OFF_RID + 256;           // 216704 B

// ---------------- preprocessed device globals ----------------
__device__ __align__(16) __nv_bfloat16 g_wqkv[360 * 128];     // qkv_w padded; q rows pre-scaled by SCALE_Q*log2e
__device__ __align__(16) __nv_bfloat16 g_projw[120 * 128];    // proj_w padded
__device__ __align__(16) float         g_bqkv[360];           // qkv bias; q part pre-scaled by SCALE_Q*log2e
__device__ __align__(16) __nv_bfloat16 g_rpb[6 * 64 * 192];   // gathered rel-pos bias [h][q][k], pre-scaled by log2e

__global__ void prep_kernel(const float* __restrict__ qkv_w, const float* __restrict__ qkv_b,
                            const float* __restrict__ proj_w, const float* __restrict__ rpb_table,
                            const int* __restrict__ rel_idx)
{
    const int i0 = blockIdx.x * blockDim.x + threadIdx.x;
    const int st = gridDim.x * blockDim.x;
    for (int t = i0; t < 360 * 128; t += st) {
        int r = t >> 7, c = t & 127;
        float v = (c < 120) ? qkv_w[r * 120 + c] : 0.f;
        if (r < 120) v *= SCALE_Q * LOG2E;
        g_wqkv[t] = __float2bfloat16(v);
    }
    for (int t = i0; t < 120 * 128; t += st) {
        int r = t >> 7, c = t & 127;
        g_projw[t] = __float2bfloat16((c < 120) ? proj_w[r * 120 + c] : 0.f);
    }
    for (int t = i0; t < 360; t += st)
        g_bqkv[t] = qkv_b[t] * ((t < 120) ? SCALE_Q * LOG2E : 1.f);
    for (int t = i0; t < 6 * 64 * 192; t += st) {
        int h = t / 12288, rem = t % 12288;          // rem = q*192 + k  (rel_idx flat order)
        g_rpb[t] = __float2bfloat16(rpb_table[rel_idx[rem] * 6 + h] * LOG2E);
    }
}

// ---------------- mma / ldmatrix helpers ----------------
DEV uint32_t s2u(const void* p) { return (uint32_t)__cvta_generic_to_shared(p); }

DEV void ldsm4(uint32_t* r, uint32_t a) {
    asm volatile("ldmatrix.sync.aligned.m8n8.x4.shared.b16 {%0,%1,%2,%3}, [%4];"
                 : "=r"(r[0]), "=r"(r[1]), "=r"(r[2]), "=r"(r[3]) : "r"(a));
}
DEV void ldsm2(uint32_t* r, uint32_t a) {
    asm volatile("ldmatrix.sync.aligned.m8n8.x2.shared.b16 {%0,%1}, [%2];"
                 : "=r"(r[0]), "=r"(r[1]) : "r"(a));
}

DEV uint32_t packbf(float a, float b) {
    __nv_bfloat162 t = __floats2bfloat162_rn(a, b);
    return *reinterpret_cast<uint32_t*>(&t);
}

DEV float ex2(float x) {
    float y;
    asm("ex2.approx.f32 %0, %1;" : "=f"(y) : "f"(x));
    return y;
}

DEV void mma16816(float* c, uint32_t a0, uint32_t a1, uint32_t a2, uint32_t a3,
                  uint32_t b0, uint32_t b1) {
    asm volatile("mma.sync.aligned.m16n8k16.row.col.f32.bf16.bf16.f32 "
                 "{%0,%1,%2,%3}, {%4,%5,%6,%7}, {%8,%9}, {%0,%1,%2,%3};\n"
                 : "+f"(c[0]), "+f"(c[1]), "+f"(c[2]), "+f"(c[3])
                 : "r"(a0), "r"(a1), "r"(a2), "r"(a3), "r"(b0), "r"(b1));
}

DEV void mma1688(float* c, uint32_t a0, uint32_t a1, uint32_t b0) {
    asm volatile("mma.sync.aligned.m16n8k8.row.col.f32.bf16.bf16.f32 "
                 "{%0,%1,%2,%3}, {%4,%5}, {%6}, {%0,%1,%2,%3};\n"
                 : "+f"(c[0]), "+f"(c[1]), "+f"(c[2]), "+f"(c[3])
                 : "r"(a0), "r"(a1), "r"(b0));
}

// 16(M) x 40(N) x 128(K): A row-major [.,LDA], B n-major [n][k] stride LDA. LDSM-fed.
DEV void gemm16x40(const __nv_bfloat16* __restrict__ A, const __nv_bfloat16* __restrict__ B,
                   float* acc, int lane)
{
    const int r16 = lane & 15, k8 = (lane >> 4) * 8;
    uint32_t aA  = s2u(A + r16 * LDA + k8);
    uint32_t aB0 = s2u(B + r16 * LDA + k8);
    uint32_t aB1 = s2u(B + (16 + r16) * LDA + k8);
    uint32_t aB2 = s2u(B + (32 + (lane & 7)) * LDA + ((lane >> 3) & 1) * 8);
#pragma unroll
    for (int ks = 0; ks < 8; ks++) {
        uint32_t av[4], b0[4], b1[4], b2[2];
        ldsm4(av, aA); ldsm4(b0, aB0); ldsm4(b1, aB1); ldsm2(b2, aB2);
        aA += 32; aB0 += 32; aB1 += 32; aB2 += 32;
        mma16816(acc + 0,  av[0], av[1], av[2], av[3], b0[0], b0[2]);
        mma16816(acc + 4,  av[0], av[1], av[2], av[3], b0[1], b0[3]);
        mma16816(acc + 8,  av[0], av[1], av[2], av[3], b1[0], b1[2]);
        mma16816(acc + 12, av[0], av[1], av[2], av[3], b1[1], b1[3]);
        mma16816(acc + 16, av[0], av[1], av[2], av[3], b2[0], b2[1]);
    }
}

// 32(M) x 40(N) x 128(K). acc[s*8+0..3] = rows 0-15 of tile s, +4..7 = rows 16-31.
DEV void gemm32x40(const __nv_bfloat16* __restrict__ A, const __nv_bfloat16* __restrict__ B,
                   float* acc, int lane)
{
    const int r16 = lane & 15, k8 = (lane >> 4) * 8;
    uint32_t aA0 = s2u(A + r16 * LDA + k8);
    uint32_t aA1 = s2u(A + (16 + r16) * LDA + k8);
    uint32_t aB0 = s2u(B + r16 * LDA + k8);
    uint32_t aB1 = s2u(B + (16 + r16) * LDA + k8);
    uint32_t aB2 = s2u(B + (32 + (lane & 7)) * LDA + ((lane >> 3) & 1) * 8);
#pragma unroll
    for (int ks = 0; ks < 8; ks++) {
        uint32_t av0[4], av1[4], b0[4], b1[4], b2[2];
        ldsm4(av0, aA0); ldsm4(av1, aA1); ldsm4(b0, aB0); ldsm4(b1, aB1); ldsm2(b2, aB2);
        aA0 += 32; aA1 += 32; aB0 += 32; aB1 += 32; aB2 += 32;
        mma16816(acc + 0,  av0[0], av0[1], av0[2], av0[3], b0[0], b0[2]);
        mma16816(acc + 4,  av1[0], av1[1], av1[2], av1[3], b0[0], b0[2]);
        mma16816(acc + 8,  av0[0], av0[1], av0[2], av0[3], b0[1], b0[3]);
        mma16816(acc + 12, av1[0], av1[1], av1[2], av1[3], b0[1], b0[3]);
        mma16816(acc + 16, av0[0], av0[1], av0[2], av0[3], b1[0], b1[2]);
        mma16816(acc + 20, av1[0], av1[1], av1[2], av1[3], b1[0], b1[2]);
        mma16816(acc + 24, av0[0], av0[1], av0[2], av0[3], b1[1], b1[3]);
        mma16816(acc + 28, av1[0], av1[1], av1[2], av1[3], b1[1], b1[3]);
        mma16816(acc + 32, av0[0], av0[1], av0[2], av0[3], b2[0], b2[1]);
        mma16816(acc + 36, av1[0], av1[1], av1[2], av1[3], b2[0], b2[1]);
    }
}

DEV void stage_w(const __nv_bfloat16* __restrict__ gsrc, __nv_bfloat16* __restrict__ sdst, int tid) {
#pragma unroll
    for (int k = 0; k < 3; k++) {
        int i = tid + k * THREADS;
        if (i < 120 * 16) {
            int r = i >> 4, c = i & 15;
            *reinterpret_cast<uint4*>(sdst + r * LDA + c * 8) =
                *reinterpret_cast<const uint4*>(gsrc + r * 128 + c * 8);
        }
    }
}

// ---------------- main fused kernel: one CTA per window ----------------
__global__ void __launch_bounds__(THREADS, 1)
swin_main_kernel(const float* __restrict__ x, const float* __restrict__ quary0,
                 const float* __restrict__ quary1, const float* __restrict__ proj_b,
                 const float* __restrict__ pm_w, const float* __restrict__ pm_b,
                 float* __restrict__ out)
{
    extern __shared__ char smem[];
    __nv_bfloat16* sX   = (__nv_bfloat16*)(smem + OFF_X);
    __nv_bfloat16* sWp  = (__nv_bfloat16*)(smem + OFF_X);    // proj W (aliases sX, staged after G2)
    __nv_bfloat16* sW   = (__nv_bfloat16*)(smem + OFF_WB);   // Wq, then Wv
    __nv_bfloat16* sO   = (__nv_bfloat16*)(smem + OFF_WB);   // attention output (alias)
    __nv_bfloat16* sK   = (__nv_bfloat16*)(smem + OFF_K);
    __nv_bfloat16* sWk  = (__nv_bfloat16*)(smem + OFF_VT);   // K weights staged (alias)
    __nv_bfloat16* sVt  = (__nv_bfloat16*)(smem + OFF_VT);
    float*         sX1  = (float*)(smem + OFF_VT);
    __nv_bfloat16* sQ   = (__nv_bfloat16*)(smem + OFF_Q);
    float*         sPred= (float*)(smem + OFF_PRED);
    int*           sRid = (int*)(smem + OFF_RID);

    const int tid  = threadIdx.x;
    const int lane = tid & 31;
    const int warp = tid >> 5;          // 0..23
    const int grp  = lane >> 2;         // 0..7
    const int tg   = lane & 3;          // 0..3
    const int wi   = blockIdx.x;
    const int wy   = wi >> 5, wx = wi & 31;
    const bool maskw = (wy == 31) || (wx == 31);
    const __nv_bfloat16 bz   = __float2bfloat16(0.f);
    const __nv_bfloat16 bone = __float2bfloat16(1.f);

    // =========== Phase A: window load (front-batched LDGs), pads, rids, W stage, pred ===========
    {
        float4 t[8];
#pragma unroll
        for (int k = 0; k < 8; k++) {
            int i = tid + k * THREADS;
            if (i < 192 * 30) {
                int n = i / 30, v = i - n * 30;
                int f = n >> 6, p = n & 63;
                int rowg = (wy * 8 + (p >> 3) + 4) & 255;
                int colg = (wx * 8 + (p & 7) + 4) & 255;
                t[k] = *reinterpret_cast<const float4*>(
                    x + ((size_t)((f * 256 + rowg) * 256 + colg)) * 120 + v * 4);
            }
        }
#pragma unroll
        for (int k = 0; k < 8; k++) {
            int i = tid + k * THREADS;
            if (i < 192 * 30) {
                int n = i / 30, v = i - n * 30;
                uint32_t* dst = reinterpret_cast<uint32_t*>(sX + n * LDA + v * 4);
                dst[0] = packbf(t[k].x, t[k].y);
                dst[1] = packbf(t[k].z, t[k].w);
            }
        }
    }
    for (int i = tid; i < 192 * 8; i += THREADS) sX[(i >> 3) * LDA + 120 + (i & 7)] = bz;
    for (int i = tid; i < 6 * 64 * 4; i += THREADS) {
        int h = i >> 8, r = (i >> 2) & 63, c = 20 + (i & 3);
        sQ[(h * 64 + r) * 24 + c] = bz;
    }
    for (int i = tid; i < 6 * 192 * 4; i += THREADS) {
        int h = i / 768, r = (i >> 2) % 192, c = 20 + (i & 3);
        sK[(h * 192 + r) * 24 + c] = bz;
    }
    if (tid < 64) {
        int r = tid >> 3, c = tid & 7;
        int rz = (wy == 31) ? ((r < 4) ? 1 : 2) : 0;
        int cz = (wx == 31) ? ((c < 4) ? 1 : 2) : 0;
        sRid[tid] = rz * 3 + cz;
    }
    stage_w(g_wqkv,             sW,  tid);   // Wq (pre-scaled incl. log2e)
    stage_w(g_wqkv + 120 * 128, sWk, tid);   // Wk -> staged in (future) sVt region

    // pred (pure fp32 from global x): wide distribution, 24 warps x 3 queries
    {
        const float pmb = pm_b[0];
#pragma unroll 1
        for (int it = 0; it < 3; it++) {
            int q = it * 24 + warp;
            float s = 0.f;
            if (q < 64) {
                int rowg = (wy * 8 + (q >> 3) + 4) & 255;
                int colg = (wx * 8 + (q & 7) + 4) & 255;
                const float* xr = x + ((size_t)((2 * 256 + rowg) * 256 + colg)) * 120;
                const float* qr = quary0 + (size_t)(wi * 64 + q) * 120;
#pragma unroll
                for (int k = 0; k < 4; k++) {
                    int ch = lane + k * 32;
                    if (ch < 120) s += fabsf(xr[ch] - qr[ch]) * pm_w[ch];
                }
            }
#pragma unroll
            for (int off = 16; off; off >>= 1) s += __shfl_xor_sync(0xffffffffu, s, off);
            if (q < 64 && lane == 0) sPred[q] = (s + pmb >= 0.f) ? 1.f : 0.f;
        }
    }
    __syncthreads();

    // =========== G1: K GEMM (warps 0..17, 32x40) + Q GEMM (warps 18..23, 32x40) ===========
    if (warp < 18) {
        const int r = warp / 3, nt = warp % 3;
        float acc[40];
#pragma unroll
        for (int i = 0; i < 40; i++) acc[i] = 0.f;
        gemm32x40(sX + r * 32 * LDA, sWk + (nt * 40) * LDA, acc, lane);
        const int t0 = r * 32 + grp;
#pragma unroll
        for (int s = 0; s < 5; s++) {
            int oc = nt * 40 + s * 8 + tg * 2;
            int hh = oc / 20, d = oc % 20;
            float b0 = g_bqkv[120 + oc], b1 = g_bqkv[121 + oc];
            __nv_bfloat16* base = sK + (hh * 192) * 24 + d;
            *reinterpret_cast<uint32_t*>(base + (t0     ) * 24) = packbf(acc[s*8+0]+b0, acc[s*8+1]+b1);
            *reinterpret_cast<uint32_t*>(base + (t0 +  8) * 24) = packbf(acc[s*8+2]+b0, acc[s*8+3]+b1);
            *reinterpret_cast<uint32_t*>(base + (t0 + 16) * 24) = packbf(acc[s*8+4]+b0, acc[s*8+5]+b1);
            *reinterpret_cast<uint32_t*>(base + (t0 + 24) * 24) = packbf(acc[s*8+6]+b0, acc[s*8+7]+b1);
        }
    } else {
        const int t = warp - 18;                  // 0..5
        const int mblk = t / 3, nt = t % 3;       // mblk: 0..1 (rows 128-159 / 160-191)
        float acc[40];
#pragma unroll
        for (int i = 0; i < 40; i++) acc[i] = 0.f;
        gemm32x40(sX + (128 + mblk * 32) * LDA, sW + (nt * 40) * LDA, acc, lane);
        const int q0 = mblk * 32 + grp;
#pragma unroll
        for (int s = 0; s < 5; s++) {
            int oc = nt * 40 + s * 8 + tg * 2;
            int hh = oc / 20, d = oc % 20;
            float b0 = g_bqkv[oc], b1 = g_bqkv[oc + 1];
            __nv_bfloat16* base = sQ + (hh * 64) * 24 + d;
            *reinterpret_cast<uint32_t*>(base + (q0     ) * 24) = packbf(acc[s*8+0]+b0, acc[s*8+1]+b1);
            *reinterpret_cast<uint32_t*>(base + (q0 +  8) * 24) = packbf(acc[s*8+2]+b0, acc[s*8+3]+b1);
            *reinterpret_cast<uint32_t*>(base + (q0 + 16) * 24) = packbf(acc[s*8+4]+b0, acc[s*8+5]+b1);
            *reinterpret_cast<uint32_t*>(base + (q0 + 24) * 24) = packbf(acc[s*8+6]+b0, acc[s*8+7]+b1);
        }
    }
    __syncthreads();

    // =========== stage Wv (over Wq) + sVt pads: d==20 gets 1.0 (ones column -> row sums) ===========
    stage_w(g_wqkv + 240 * 128, sW, tid);
    for (int i = tid; i < 6 * 4 * 192; i += THREADS) {
        int h = i / 768, rem = i % 768;
        int d = 20 + rem / 192, k = rem % 192;
        sVt[(h * 24 + d) * LDVT + k] = (d == 20) ? bone : bz;
    }
    __syncthreads();

    // =========== G2: V GEMM (warps 0..17, 32x40), stored transposed ===========
    if (warp < 18) {
        const int r = warp / 3, nt = warp % 3;
        float acc[40];
#pragma unroll
        for (int i = 0; i < 40; i++) acc[i] = 0.f;
        gemm32x40(sX + r * 32 * LDA, sW + (nt * 40) * LDA, acc, lane);
        const int t0 = r * 32 + grp;
#pragma unroll
        for (int s = 0; s < 5; s++) {
            int oc = nt * 40 + s * 8 + tg * 2;
            int hh = oc / 20, d = oc % 20;
            float b0 = g_bqkv[240 + oc], b1 = g_bqkv[241 + oc];
            __nv_bfloat16* r0 = sVt + (hh * 24 + d) * LDVT;
            __nv_bfloat16* r1 = sVt + (hh * 24 + d + 1) * LDVT;
            r0[t0     ] = __float2bfloat16(acc[s*8+0] + b0);
            r1[t0     ] = __float2bfloat16(acc[s*8+1] + b1);
            r0[t0 +  8] = __float2bfloat16(acc[s*8+2] + b0);
            r1[t0 +  8] = __float2bfloat16(acc[s*8+3] + b1);
            r0[t0 + 16] = __float2bfloat16(acc[s*8+4] + b0);
            r1[t0 + 16] = __float2bfloat16(acc[s*8+5] + b1);
            r0[t0 + 24] = __float2bfloat16(acc[s*8+6] + b0);
            r1[t0 + 24] = __float2bfloat16(acc[s*8+7] + b1);
        }
    }
    __syncthreads();

    // sX dead: stage proj W (LDG hides under attention); zero sO pads
    stage_w(g_projw, sWp, tid);
    for (int i = tid; i < 64 * 16; i += THREADS) sO[(i >> 4) * LDA + 120 + (i & 15)] = bz;

    // =========== attention: 24 warp-tasks, 4x48 key chunks, no-max softmax (log2 domain) ===========
    {
        const int h    = warp >> 2;          // 0..5
        const int mblk = warp & 3;           // 0..3
        const int q0   = mblk * 16 + grp;
        const int q1   = q0 + 8;

        uint32_t aq[6];
        {
            const __nv_bfloat16* Qb = sQ + (h * 64 + mblk * 16) * 24;
            ldsm4(aq,     s2u(Qb + (lane & 15) * 24 + (lane >> 4) * 8));
            ldsm2(aq + 4, s2u(Qb + (lane & 15) * 24 + 16));
        }

        float O[12];
#pragma unroll
        for (int i = 0; i < 12; i++) O[i] = 0.f;
        const int rq0 = sRid[q0], rq1 = sRid[q1];

#pragma unroll 1
        for (int c = 0; c < 4; c++) {
            uint32_t ru0[6], ru1[6];
            {
                const uint32_t* rp0 = reinterpret_cast<const uint32_t*>(g_rpb + (h * 64 + q0) * 192 + c * 48) + tg;
                const uint32_t* rp1 = reinterpret_cast<const uint32_t*>(g_rpb + (h * 64 + q1) * 192 + c * 48) + tg;
#pragma unroll
                for (int j = 0; j < 6; j++) { ru0[j] = rp0[j * 4]; ru1[j] = rp1[j * 4]; }
            }

            float s[24];
#pragma unroll
            for (int i = 0; i < 24; i++) s[i] = 0.f;

            const __nv_bfloat16* Kh = sK + (h * 192 + c * 48) * 24;
            {
                uint32_t bp = s2u(Kh + (lane & 15) * 24 + (lane >> 4) * 8);
#pragma unroll
                for (int p = 0; p < 3; p++) {
                    uint32_t kb[4];
                    ldsm4(kb, bp + p * 768);          // 16 tokens * 48B
                    mma16816(s + (2*p  ) * 4, aq[0], aq[1], aq[2], aq[3], kb[0], kb[2]);
                    mma16816(s + (2*p+1) * 4, aq[0], aq[1], aq[2], aq[3], kb[1], kb[3]);
                }
                uint32_t kt[6];
                ldsm4(kt,     s2u(Kh + lane * 24 + 16));
                ldsm2(kt + 4, s2u(Kh + (32 + (lane & 15)) * 24 + 16));
#pragma unroll
                for (int j = 0; j < 6; j++) mma1688(s + j * 4, aq[4], aq[5], kt[j]);
            }

#pragma unroll
            for (int j = 0; j < 6; j++) {
                float2 f0 = __bfloat1622float2(*reinterpret_cast<__nv_bfloat162*>(&ru0[j]));
                float2 f1 = __bfloat1622float2(*reinterpret_cast<__nv_bfloat162*>(&ru1[j]));
                s[j*4+0] += f0.x; s[j*4+1] += f0.y;
                s[j*4+2] += f1.x; s[j*4+3] += f1.y;
            }

            if (maskw) {
#pragma unroll
                for (int j = 0; j < 6; j++) {
                    int kc = (c * 48 + j * 8 + tg * 2) & 63;
                    int rk0 = sRid[kc], rk1 = sRid[kc + 1];
                    if (rk0 != rq0) s[j*4+0] -= MASKC;
                    if (rk1 != rq0) s[j*4+1] -= MASKC;
                    if (rk0 != rq1) s[j*4+2] -= MASKC;
                    if (rk1 != rq1) s[j*4+3] -= MASKC;
                }
            }

#pragma unroll
            for (int i = 0; i < 24; i++) s[i] = ex2(s[i]);

            const __nv_bfloat16* Vh = sVt + (h * 24) * LDVT + c * 48;
            uint32_t pv4 = s2u(Vh + (lane & 15) * LDVT + (lane >> 4) * 8);
            uint32_t pv2 = s2u(Vh + (16 + (lane & 7)) * LDVT + ((lane >> 3) & 1) * 8);
#pragma unroll
            for (int kk = 0; kk < 3; kk++) {
                uint32_t vb[6];
                ldsm4(vb,     pv4 + kk * 32);
                ldsm2(vb + 4, pv2 + kk * 32);
                uint32_t a0 = packbf(s[kk*8+0], s[kk*8+1]);
                uint32_t a1 = packbf(s[kk*8+2], s[kk*8+3]);
                uint32_t a2 = packbf(s[kk*8+4], s[kk*8+5]);
                uint32_t a3 = packbf(s[kk*8+6], s[kk*8+7]);
                mma16816(O + 0, a0, a1, a2, a3, vb[0], vb[2]);
                mma16816(O + 4, a0, a1, a2, a3, vb[1], vb[3]);
                mma16816(O + 8, a0, a1, a2, a3, vb[4], vb[5]);
            }
        }

        // row sums live in col 20 = O[8] (q0) / O[10] (q1) of lanes with tg==2
        const int src = (lane & ~3) | 2;
        const float inv0 = 1.f / __shfl_sync(0xffffffffu, O[8],  src);
        const float inv1 = 1.f / __shfl_sync(0xffffffffu, O[10], src);
#pragma unroll
        for (int nt = 0; nt < 3; nt++) {
            int d = nt * 8 + tg * 2;
            if (d < 20) {
                *reinterpret_cast<uint32_t*>(sO + q0 * LDA + h * 20 + d) = packbf(O[nt*4+0]*inv0, O[nt*4+1]*inv0);
                *reinterpret_cast<uint32_t*>(sO + q1 * LDA + h * 20 + d) = packbf(O[nt*4+2]*inv1, O[nt*4+3]*inv1);
            }
        }
    }
    __syncthreads();

    // =========== proj GEMM + blend (proj W staged in sWp during attention) ===========
    if (warp < 12) {
        const int mt = warp & 3, nt = warp >> 2;
        const int q0 = mt * 16 + grp, q1 = q0 + 8;
        float acc[20];
#pragma unroll
        for (int i = 0; i < 20; i++) acc[i] = 0.f;
        gemm16x40(sO + mt * 16 * LDA, sWp + (nt * 40) * LDA, acc, lane);
#pragma unroll
        for (int s = 0; s < 5; s++) {
            int oc = nt * 40 + s * 8 + tg * 2;
            float b0 = proj_b[oc], b1 = proj_b[oc + 1];
            *reinterpret_cast<float2*>(sX1 + q0 * LDX1 + oc) = make_float2(acc[s*4+0]+b0, acc[s*4+1]+b1);
            *reinterpret_cast<float2*>(sX1 + q1 * LDX1 + oc) = make_float2(acc[s*4+2]+b0, acc[s*4+3]+b1);
        }
    }
    __syncthreads();

    // =========== scatter store: token p -> out[(wy*8+r+4)&255][(wx*8+c+4)&255][121] ===========
    for (int idx = tid; idx < 64 * 121; idx += THREADS) {
        int p = idx / 121, c = idx - p * 121;
        int rowg = (wy * 8 + (p >> 3) + 4) & 255;
        int colg = (wx * 8 + (p & 7) + 4) & 255;
        float pv = sPred[p];
        float v;
        if (c == 120) v = pv;
        else v = (pv != 0.f) ? sX1[p * LDX1 + c] : quary1[(size_t)(wi * 64 + p) * 120 + c];
        out[(size_t)(rowg * 256 + colg) * 121 + c] = v;
    }
}

// ---------------- launch ----------------
extern "C" void kernel_launch(void* const* d_in, const int* in_sizes, int n_in,
                              void* d_out, int out_size)
{
    (void)in_sizes; (void)n_in; (void)out_size;
    const float* x        = (const float*)d_in[0];
    const float* quary0   = (const float*)d_in[1];
    const float* quary1   = (const float*)d_in[2];
    const float* qkv_w    = (const float*)d_in[3];
    const float* qkv_b    = (const float*)d_in[4];
    const float* proj_w   = (const float*)d_in[5];
    const float* proj_b   = (const float*)d_in[6];
    const float* rpb_tab  = (const float*)d_in[7];
    const float* pm_w     = (const float*)d_in[8];
    const float* pm_b     = (const float*)d_in[9];
    // d_in[10] = attn_mask : intentionally unused (recomputed analytically)
    const int*   rel_idx  = (const int*)d_in[11];
    float* out = (float*)d_out;

    cudaFuncSetAttribute(swin_main_kernel, cudaFuncAttributeMaxDynamicSharedMemorySize, SMEM_TOTAL);

    prep_kernel<<<128, 256>>>(qkv_w, qkv_b, proj_w, rpb_tab, rel_idx);
    swin_main_kernel<<<1024, THREADS, SMEM_TOTAL>>>(x, quary0, quary1, proj_b, pm_w, pm_b, out);
}

// round 16
// speedup vs baseline: 1.7187x; 1.0464x over previous
#include <cuda_runtime.h>
#include <cuda_bf16.h>
#include <cstdint>

#define DEV __device__ __forceinline__

static constexpr int   THREADS = 768;   // 24 warps (RF-capped sweet spot)
static constexpr float SCALE_Q = 0.223606797749978969f;   // 20^-0.5
static constexpr float LOG2E   = 1.4426950408889634f;
static constexpr float MASKC   = 144.26950408889634f;     // 100 * log2(e)

// ---------------- shared memory layout (bytes) ----------------
static constexpr int LDA  = 136;   // elems; 272B rows -> conflict-free LDSM
static constexpr int LDVT = 200;   // 400B rows
static constexpr int LDX1 = 124;

static constexpr int OFF_X    = 0;                         // sX bf16[192][136] | later proj W
static constexpr int OFF_WB   = OFF_X  + 192 * LDA * 2;    // sW (Wq, later Wv) | alias sO bf16[64][136]
static constexpr int OFF_K    = OFF_WB + 120 * LDA * 2;    // sK bf16[6][192][24]
static constexpr int OFF_VT   = OFF_K  + 6 * 192 * 24 * 2; // Wk staging, then sVt bf16[6][24][200] | alias sX1 f32[64][124]
static constexpr int OFF_Q    = OFF_VT + 6 * 24 * LDVT * 2;// sQ bf16[6][64][24]
static constexpr int OFF_PRED = OFF_Q  + 6 * 64 * 24 * 2;  // f32[64]
static constexpr int OFF_RID  = OFF_PRED + 256;            // int[64]
static constexpr int SMEM_TOTAL = OFF_RID + 256;           // 216704 B

// ---------------- preprocessed device globals ----------------
__device__ __align__(16) __nv_bfloat16 g_wqkv[360 * 128];     // qkv_w padded; q rows pre-scaled by SCALE_Q*log2e
__device__ __align__(16) __nv_bfloat16 g_projw[120 * 128];    // proj_w padded
__device__ __align__(16) float         g_bqkv[360];           // qkv bias; q part pre-scaled by SCALE_Q*log2e
__device__ __align__(16) __nv_bfloat16 g_rpb[6 * 64 * 192];   // gathered rel-pos bias [h][q][k], pre-scaled by log2e

__global__ void prep_kernel(const float* __restrict__ qkv_w, const float* __restrict__ qkv_b,
                            const float* __restrict__ proj_w, const float* __restrict__ rpb_table,
                            const int* __restrict__ rel_idx)
{
    const int i0 = blockIdx.x * blockDim.x + threadIdx.x;
    const int st = gridDim.x * blockDim.x;
    for (int t = i0; t < 360 * 128; t += st) {
        int r = t >> 7, c = t & 127;
        float v = (c < 120) ? qkv_w[r * 120 + c] : 0.f;
        if (r < 120) v *= SCALE_Q * LOG2E;
        g_wqkv[t] = __float2bfloat16(v);
    }
    for (int t = i0; t < 120 * 128; t += st) {
        int r = t >> 7, c = t & 127;
        g_projw[t] = __float2bfloat16((c < 120) ? proj_w[r * 120 + c] : 0.f);
    }
    for (int t = i0; t < 360; t += st)
        g_bqkv[t] = qkv_b[t] * ((t < 120) ? SCALE_Q * LOG2E : 1.f);
    for (int t = i0; t < 6 * 64 * 192; t += st) {
        int h = t / 12288, rem = t % 12288;          // rem = q*192 + k  (rel_idx flat order)
        g_rpb[t] = __float2bfloat16(rpb_table[rel_idx[rem] * 6 + h] * LOG2E);
    }
}

// ---------------- mma / ldmatrix helpers ----------------
DEV uint32_t s2u(const void* p) { return (uint32_t)__cvta_generic_to_shared(p); }

DEV void ldsm4(uint32_t* r, uint32_t a) {
    asm volatile("ldmatrix.sync.aligned.m8n8.x4.shared.b16 {%0,%1,%2,%3}, [%4];"
                 : "=r"(r[0]), "=r"(r[1]), "=r"(r[2]), "=r"(r[3]) : "r"(a));
}
DEV void ldsm2(uint32_t* r, uint32_t a) {
    asm volatile("ldmatrix.sync.aligned.m8n8.x2.shared.b16 {%0,%1}, [%2];"
                 : "=r"(r[0]), "=r"(r[1]) : "r"(a));
}

DEV uint32_t packbf(float a, float b) {
    __nv_bfloat162 t = __floats2bfloat162_rn(a, b);
    return *reinterpret_cast<uint32_t*>(&t);
}

DEV float ex2(float x) {
    float y;
    asm("ex2.approx.f32 %0, %1;" : "=f"(y) : "f"(x));
    return y;
}

DEV void mma16816(float* c, uint32_t a0, uint32_t a1, uint32_t a2, uint32_t a3,
                  uint32_t b0, uint32_t b1) {
    asm volatile("mma.sync.aligned.m16n8k16.row.col.f32.bf16.bf16.f32 "
                 "{%0,%1,%2,%3}, {%4,%5,%6,%7}, {%8,%9}, {%0,%1,%2,%3};\n"
                 : "+f"(c[0]), "+f"(c[1]), "+f"(c[2]), "+f"(c[3])
                 : "r"(a0), "r"(a1), "r"(a2), "r"(a3), "r"(b0), "r"(b1));
}

DEV void mma1688(float* c, uint32_t a0, uint32_t a1, uint32_t b0) {
    asm volatile("mma.sync.aligned.m16n8k8.row.col.f32.bf16.bf16.f32 "
                 "{%0,%1,%2,%3}, {%4,%5}, {%6}, {%0,%1,%2,%3};\n"
                 : "+f"(c[0]), "+f"(c[1]), "+f"(c[2]), "+f"(c[3])
                 : "r"(a0), "r"(a1), "r"(b0));
}

// 16(M) x 40(N) x 128(K): A row-major [.,LDA], B n-major [n][k] stride LDA. LDSM-fed.
DEV void gemm16x40(const __nv_bfloat16* __restrict__ A, const __nv_bfloat16* __restrict__ B,
                   float* acc, int lane)
{
    const int r16 = lane & 15, k8 = (lane >> 4) * 8;
    uint32_t aA  = s2u(A + r16 * LDA + k8);
    uint32_t aB0 = s2u(B + r16 * LDA + k8);
    uint32_t aB1 = s2u(B + (16 + r16) * LDA + k8);
    uint32_t aB2 = s2u(B + (32 + (lane & 7)) * LDA + ((lane >> 3) & 1) * 8);
#pragma unroll
    for (int ks = 0; ks < 8; ks++) {
        uint32_t av[4], b0[4], b1[4], b2[2];
        ldsm4(av, aA); ldsm4(b0, aB0); ldsm4(b1, aB1); ldsm2(b2, aB2);
        aA += 32; aB0 += 32; aB1 += 32; aB2 += 32;
        mma16816(acc + 0,  av[0], av[1], av[2], av[3], b0[0], b0[2]);
        mma16816(acc + 4,  av[0], av[1], av[2], av[3], b0[1], b0[3]);
        mma16816(acc + 8,  av[0], av[1], av[2], av[3], b1[0], b1[2]);
        mma16816(acc + 12, av[0], av[1], av[2], av[3], b1[1], b1[3]);
        mma16816(acc + 16, av[0], av[1], av[2], av[3], b2[0], b2[1]);
    }
}

// 32(M) x 40(N) x 128(K). acc[s*8+0..3] = rows 0-15 of tile s, +4..7 = rows 16-31.
DEV void gemm32x40(const __nv_bfloat16* __restrict__ A, const __nv_bfloat16* __restrict__ B,
                   float* acc, int lane)
{
    const int r16 = lane & 15, k8 = (lane >> 4) * 8;
    uint32_t aA0 = s2u(A + r16 * LDA + k8);
    uint32_t aA1 = s2u(A + (16 + r16) * LDA + k8);
    uint32_t aB0 = s2u(B + r16 * LDA + k8);
    uint32_t aB1 = s2u(B + (16 + r16) * LDA + k8);
    uint32_t aB2 = s2u(B + (32 + (lane & 7)) * LDA + ((lane >> 3) & 1) * 8);
#pragma unroll
    for (int ks = 0; ks < 8; ks++) {
        uint32_t av0[4], av1[4], b0[4], b1[4], b2[2];
        ldsm4(av0, aA0); ldsm4(av1, aA1); ldsm4(b0, aB0); ldsm4(b1, aB1); ldsm2(b2, aB2);
        aA0 += 32; aA1 += 32; aB0 += 32; aB1 += 32; aB2 += 32;
        mma16816(acc + 0,  av0[0], av0[1], av0[2], av0[3], b0[0], b0[2]);
        mma16816(acc + 4,  av1[0], av1[1], av1[2], av1[3], b0[0], b0[2]);
        mma16816(acc + 8,  av0[0], av0[1], av0[2], av0[3], b0[1], b0[3]);
        mma16816(acc + 12, av1[0], av1[1], av1[2], av1[3], b0[1], b0[3]);
        mma16816(acc + 16, av0[0], av0[1], av0[2], av0[3], b1[0], b1[2]);
        mma16816(acc + 20, av1[0], av1[1], av1[2], av1[3], b1[0], b1[2]);
        mma16816(acc + 24, av0[0], av0[1], av0[2], av0[3], b1[1], b1[3]);
        mma16816(acc + 28, av1[0], av1[1], av1[2], av1[3], b1[1], b1[3]);
        mma16816(acc + 32, av0[0], av0[1], av0[2], av0[3], b2[0], b2[1]);
        mma16816(acc + 36, av1[0], av1[1], av1[2], av1[3], b2[0], b2[1]);
    }
}

DEV void stage_w(const __nv_bfloat16* __restrict__ gsrc, __nv_bfloat16* __restrict__ sdst, int tid) {
#pragma unroll
    for (int k = 0; k < 3; k++) {
        int i = tid + k * THREADS;
        if (i < 120 * 16) {
            int r = i >> 4, c = i & 15;
            *reinterpret_cast<uint4*>(sdst + r * LDA + c * 8) =
                *reinterpret_cast<const uint4*>(gsrc + r * 128 + c * 8);
        }
    }
}

// ---------------- main fused kernel: one CTA per window ----------------
__global__ void __launch_bounds__(THREADS, 1)
swin_main_kernel(const float* __restrict__ x, const float* __restrict__ quary0,
                 const float* __restrict__ quary1, const float* __restrict__ proj_b,
                 const float* __restrict__ pm_w, const float* __restrict__ pm_b,
                 float* __restrict__ out)
{
    extern __shared__ char smem[];
    __nv_bfloat16* sX   = (__nv_bfloat16*)(smem + OFF_X);
    __nv_bfloat16* sWp  = (__nv_bfloat16*)(smem + OFF_X);    // proj W (aliases sX, staged after G2)
    __nv_bfloat16* sW   = (__nv_bfloat16*)(smem + OFF_WB);   // Wq, then Wv
    __nv_bfloat16* sO   = (__nv_bfloat16*)(smem + OFF_WB);   // attention output (alias)
    __nv_bfloat16* sK   = (__nv_bfloat16*)(smem + OFF_K);
    __nv_bfloat16* sWk  = (__nv_bfloat16*)(smem + OFF_VT);   // K weights staged (alias)
    __nv_bfloat16* sVt  = (__nv_bfloat16*)(smem + OFF_VT);
    float*         sX1  = (float*)(smem + OFF_VT);
    __nv_bfloat16* sQ   = (__nv_bfloat16*)(smem + OFF_Q);
    float*         sPred= (float*)(smem + OFF_PRED);
    int*           sRid = (int*)(smem + OFF_RID);

    const int tid  = threadIdx.x;
    const int lane = tid & 31;
    const int warp = tid >> 5;          // 0..23
    const int grp  = lane >> 2;         // 0..7
    const int tg   = lane & 3;          // 0..3
    const int wi   = blockIdx.x;
    const int wy   = wi >> 5, wx = wi & 31;
    const bool maskw = (wy == 31) || (wx == 31);
    const __nv_bfloat16 bz   = __float2bfloat16(0.f);
    const __nv_bfloat16 bone = __float2bfloat16(1.f);

    // =========== Phase A: window load (front-batched LDGs), pads, rids, W stage, pred ===========
    {
        float4 t[8];
#pragma unroll
        for (int k = 0; k < 8; k++) {
            int i = tid + k * THREADS;
            if (i < 192 * 30) {
                int n = i / 30, v = i - n * 30;
                int f = n >> 6, p = n & 63;
                int rowg = (wy * 8 + (p >> 3) + 4) & 255;
                int colg = (wx * 8 + (p & 7) + 4) & 255;
                t[k] = *reinterpret_cast<const float4*>(
                    x + ((size_t)((f * 256 + rowg) * 256 + colg)) * 120 + v * 4);
            }
        }
#pragma unroll
        for (int k = 0; k < 8; k++) {
            int i = tid + k * THREADS;
            if (i < 192 * 30) {
                int n = i / 30, v = i - n * 30;
                uint32_t* dst = reinterpret_cast<uint32_t*>(sX + n * LDA + v * 4);
                dst[0] = packbf(t[k].x, t[k].y);
                dst[1] = packbf(t[k].z, t[k].w);
            }
        }
    }
    for (int i = tid; i < 192 * 8; i += THREADS) sX[(i >> 3) * LDA + 120 + (i & 7)] = bz;
    for (int i = tid; i < 6 * 64 * 4; i += THREADS) {
        int h = i >> 8, r = (i >> 2) & 63, c = 20 + (i & 3);
        sQ[(h * 64 + r) * 24 + c] = bz;
    }
    for (int i = tid; i < 6 * 192 * 4; i += THREADS) {
        int h = i / 768, r = (i >> 2) % 192, c = 20 + (i & 3);
        sK[(h * 192 + r) * 24 + c] = bz;
    }
    if (tid < 64) {
        int r = tid >> 3, c = tid & 7;
        int rz = (wy == 31) ? ((r < 4) ? 1 : 2) : 0;
        int cz = (wx == 31) ? ((c < 4) ? 1 : 2) : 0;
        sRid[tid] = rz * 3 + cz;
    }
    stage_w(g_wqkv,             sW,  tid);   // Wq (pre-scaled incl. log2e)
    stage_w(g_wqkv + 120 * 128, sWk, tid);   // Wk -> staged in (future) sVt region

    // pred (pure fp32 from global x): 24 warps x 3 queries, fully unrolled so LDGs hoist
    {
        const float pmb = pm_b[0];
#pragma unroll
        for (int it = 0; it < 3; it++) {
            int q = it * 24 + warp;
            float s = 0.f;
            if (q < 64) {
                int rowg = (wy * 8 + (q >> 3) + 4) & 255;
                int colg = (wx * 8 + (q & 7) + 4) & 255;
                const float* xr = x + ((size_t)((2 * 256 + rowg) * 256 + colg)) * 120;
                const float* qr = quary0 + (size_t)(wi * 64 + q) * 120;
#pragma unroll
                for (int k = 0; k < 4; k++) {
                    int ch = lane + k * 32;
                    if (ch < 120) s += fabsf(xr[ch] - qr[ch]) * pm_w[ch];
                }
            }
#pragma unroll
            for (int off = 16; off; off >>= 1) s += __shfl_xor_sync(0xffffffffu, s, off);
            if (q < 64 && lane == 0) sPred[q] = (s + pmb >= 0.f) ? 1.f : 0.f;
        }
    }
    __syncthreads();

    // =========== G1: K GEMM (warps 0..17, 32x40) + Q GEMM (warps 18..23, 32x40) ===========
    if (warp < 18) {
        const int r = warp / 3, nt = warp % 3;
        float acc[40];
#pragma unroll
        for (int i = 0; i < 40; i++) acc[i] = 0.f;
        gemm32x40(sX + r * 32 * LDA, sWk + (nt * 40) * LDA, acc, lane);
        const int t0 = r * 32 + grp;
#pragma unroll
        for (int s = 0; s < 5; s++) {
            int oc = nt * 40 + s * 8 + tg * 2;
            int hh = oc / 20, d = oc % 20;
            float b0 = g_bqkv[120 + oc], b1 = g_bqkv[121 + oc];
            __nv_bfloat16* base = sK + (hh * 192) * 24 + d;
            *reinterpret_cast<uint32_t*>(base + (t0     ) * 24) = packbf(acc[s*8+0]+b0, acc[s*8+1]+b1);
            *reinterpret_cast<uint32_t*>(base + (t0 +  8) * 24) = packbf(acc[s*8+2]+b0, acc[s*8+3]+b1);
            *reinterpret_cast<uint32_t*>(base + (t0 + 16) * 24) = packbf(acc[s*8+4]+b0, acc[s*8+5]+b1);
            *reinterpret_cast<uint32_t*>(base + (t0 + 24) * 24) = packbf(acc[s*8+6]+b0, acc[s*8+7]+b1);
        }
    } else {
        const int t = warp - 18;                  // 0..5
        const int mblk = t / 3, nt = t % 3;       // mblk: 0..1 (rows 128-159 / 160-191)
        float acc[40];
#pragma unroll
        for (int i = 0; i < 40; i++) acc[i] = 0.f;
        gemm32x40(sX + (128 + mblk * 32) * LDA, sW + (nt * 40) * LDA, acc, lane);
        const int q0 = mblk * 32 + grp;
#pragma unroll
        for (int s = 0; s < 5; s++) {
            int oc = nt * 40 + s * 8 + tg * 2;
            int hh = oc / 20, d = oc % 20;
            float b0 = g_bqkv[oc], b1 = g_bqkv[oc + 1];
            __nv_bfloat16* base = sQ + (hh * 64) * 24 + d;
            *reinterpret_cast<uint32_t*>(base + (q0     ) * 24) = packbf(acc[s*8+0]+b0, acc[s*8+1]+b1);
            *reinterpret_cast<uint32_t*>(base + (q0 +  8) * 24) = packbf(acc[s*8+2]+b0, acc[s*8+3]+b1);
            *reinterpret_cast<uint32_t*>(base + (q0 + 16) * 24) = packbf(acc[s*8+4]+b0, acc[s*8+5]+b1);
            *reinterpret_cast<uint32_t*>(base + (q0 + 24) * 24) = packbf(acc[s*8+6]+b0, acc[s*8+7]+b1);
        }
    }
    __syncthreads();

    // =========== stage Wv (over Wq) + sVt pads: d==20 gets 1.0 (ones column -> row sums) ===========
    stage_w(g_wqkv + 240 * 128, sW, tid);
    for (int i = tid; i < 6 * 4 * 192; i += THREADS) {
        int h = i / 768, rem = i % 768;
        int d = 20 + rem / 192, k = rem % 192;
        sVt[(h * 24 + d) * LDVT + k] = (d == 20) ? bone : bz;
    }
    __syncthreads();

    // =========== G2: V GEMM (warps 0..17, 32x40), stored transposed ===========
    if (warp < 18) {
        const int r = warp / 3, nt = warp % 3;
        float acc[40];
#pragma unroll
        for (int i = 0; i < 40; i++) acc[i] = 0.f;
        gemm32x40(sX + r * 32 * LDA, sW + (nt * 40) * LDA, acc, lane);
        const int t0 = r * 32 + grp;
#pragma unroll
        for (int s = 0; s < 5; s++) {
            int oc = nt * 40 + s * 8 + tg * 2;
            int hh = oc / 20, d = oc % 20;
            float b0 = g_bqkv[240 + oc], b1 = g_bqkv[241 + oc];
            __nv_bfloat16* r0 = sVt + (hh * 24 + d) * LDVT;
            __nv_bfloat16* r1 = sVt + (hh * 24 + d + 1) * LDVT;
            r0[t0     ] = __float2bfloat16(acc[s*8+0] + b0);
            r1[t0     ] = __float2bfloat16(acc[s*8+1] + b1);
            r0[t0 +  8] = __float2bfloat16(acc[s*8+2] + b0);
            r1[t0 +  8] = __float2bfloat16(acc[s*8+3] + b1);
            r0[t0 + 16] = __float2bfloat16(acc[s*8+4] + b0);
            r1[t0 + 16] = __float2bfloat16(acc[s*8+5] + b1);
            r0[t0 + 24] = __float2bfloat16(acc[s*8+6] + b0);
            r1[t0 + 24] = __float2bfloat16(acc[s*8+7] + b1);
        }
    }
    __syncthreads();

    // sX dead: stage proj W (LDG hides under attention); zero sO pads
    stage_w(g_projw, sWp, tid);
    for (int i = tid; i < 64 * 16; i += THREADS) sO[(i >> 4) * LDA + 120 + (i & 15)] = bz;

    // =========== attention: 24 warp-tasks, 4x48 key chunks, no-max softmax (log2 domain) ===========
    {
        const int h    = warp >> 2;          // 0..5
        const int mblk = warp & 3;           // 0..3
        const int q0   = mblk * 16 + grp;
        const int q1   = q0 + 8;

        uint32_t aq[6];
        {
            const __nv_bfloat16* Qb = sQ + (h * 64 + mblk * 16) * 24;
            ldsm4(aq,     s2u(Qb + (lane & 15) * 24 + (lane >> 4) * 8));
            ldsm2(aq + 4, s2u(Qb + (lane & 15) * 24 + 16));
        }

        float O[12];
#pragma unroll
        for (int i = 0; i < 12; i++) O[i] = 0.f;
        const int rq0 = sRid[q0], rq1 = sRid[q1];

#pragma unroll 1
        for (int c = 0; c < 4; c++) {
            uint32_t ru0[6], ru1[6];
            {
                const uint32_t* rp0 = reinterpret_cast<const uint32_t*>(g_rpb + (h * 64 + q0) * 192 + c * 48) + tg;
                const uint32_t* rp1 = reinterpret_cast<const uint32_t*>(g_rpb + (h * 64 + q1) * 192 + c * 48) + tg;
#pragma unroll
                for (int j = 0; j < 6; j++) { ru0[j] = rp0[j * 4]; ru1[j] = rp1[j * 4]; }
            }

            float s[24];
#pragma unroll
            for (int i = 0; i < 24; i++) s[i] = 0.f;

            const __nv_bfloat16* Kh = sK + (h * 192 + c * 48) * 24;
            {
                uint32_t bp = s2u(Kh + (lane & 15) * 24 + (lane >> 4) * 8);
#pragma unroll
                for (int p = 0; p < 3; p++) {
                    uint32_t kb[4];
                    ldsm4(kb, bp + p * 768);          // 16 tokens * 48B
                    mma16816(s + (2*p  ) * 4, aq[0], aq[1], aq[2], aq[3], kb[0], kb[2]);
                    mma16816(s + (2*p+1) * 4, aq[0], aq[1], aq[2], aq[3], kb[1], kb[3]);
                }
                uint32_t kt[6];
                ldsm4(kt,     s2u(Kh + lane * 24 + 16));
                ldsm2(kt + 4, s2u(Kh + (32 + (lane & 15)) * 24 + 16));
#pragma unroll
                for (int j = 0; j < 6; j++) mma1688(s + j * 4, aq[4], aq[5], kt[j]);
            }

#pragma unroll
            for (int j = 0; j < 6; j++) {
                float2 f0 = __bfloat1622float2(*reinterpret_cast<__nv_bfloat162*>(&ru0[j]));
                float2 f1 = __bfloat1622float2(*reinterpret_cast<__nv_bfloat162*>(&ru1[j]));
                s[j*4+0] += f0.x; s[j*4+1] += f0.y;
                s[j*4+2] += f1.x; s[j*4+3] += f1.y;
            }

            if (maskw) {
#pragma unroll
                for (int j = 0; j < 6; j++) {
                    int kc = (c * 48 + j * 8 + tg * 2) & 63;
                    int rk0 = sRid[kc], rk1 = sRid[kc + 1];
                    if (rk0 != rq0) s[j*4+0] -= MASKC;
                    if (rk1 != rq0) s[j*4+1] -= MASKC;
                    if (rk0 != rq1) s[j*4+2] -= MASKC;
                    if (rk1 != rq1) s[j*4+3] -= MASKC;
                }
            }

#pragma unroll
            for (int i = 0; i < 24; i++) s[i] = ex2(s[i]);

            const __nv_bfloat16* Vh = sVt + (h * 24) * LDVT + c * 48;
            uint32_t pv4 = s2u(Vh + (lane & 15) * LDVT + (lane >> 4) * 8);
            uint32_t pv2 = s2u(Vh + (16 + (lane & 7)) * LDVT + ((lane >> 3) & 1) * 8);
#pragma unroll
            for (int kk = 0; kk < 3; kk++) {
                uint32_t vb[6];
                ldsm4(vb,     pv4 + kk * 32);
                ldsm2(vb + 4, pv2 + kk * 32);
                uint32_t a0 = packbf(s[kk*8+0], s[kk*8+1]);
                uint32_t a1 = packbf(s[kk*8+2], s[kk*8+3]);
                uint32_t a2 = packbf(s[kk*8+4], s[kk*8+5]);
                uint32_t a3 = packbf(s[kk*8+6], s[kk*8+7]);
                mma16816(O + 0, a0, a1, a2, a3, vb[0], vb[2]);
                mma16816(O + 4, a0, a1, a2, a3, vb[1], vb[3]);
                mma16816(O + 8, a0, a1, a2, a3, vb[4], vb[5]);
            }
        }

        // row sums live in col 20 = O[8] (q0) / O[10] (q1) of lanes with tg==2
        const int src = (lane & ~3) | 2;
        const float inv0 = 1.f / __shfl_sync(0xffffffffu, O[8],  src);
        const float inv1 = 1.f / __shfl_sync(0xffffffffu, O[10], src);
#pragma unroll
        for (int nt = 0; nt < 3; nt++) {
            int d = nt * 8 + tg * 2;
            if (d < 20) {
                *reinterpret_cast<uint32_t*>(sO + q0 * LDA + h * 20 + d) = packbf(O[nt*4+0]*inv0, O[nt*4+1]*inv0);
                *reinterpret_cast<uint32_t*>(sO + q1 * LDA + h * 20 + d) = packbf(O[nt*4+2]*inv1, O[nt*4+3]*inv1);
            }
        }
    }
    __syncthreads();

    // =========== proj GEMM + blend (proj W staged in sWp during attention) ===========
    if (warp < 12) {
        const int mt = warp & 3, nt = warp >> 2;
        const int q0 = mt * 16 + grp, q1 = q0 + 8;
        float acc[20];
#pragma unroll
        for (int i = 0; i < 20; i++) acc[i] = 0.f;
        gemm16x40(sO + mt * 16 * LDA, sWp + (nt * 40) * LDA, acc, lane);
#pragma unroll
        for (int s = 0; s < 5; s++) {
            int oc = nt * 40 + s * 8 + tg * 2;
            float b0 = proj_b[oc], b1 = proj_b[oc + 1];
            *reinterpret_cast<float2*>(sX1 + q0 * LDX1 + oc) = make_float2(acc[s*4+0]+b0, acc[s*4+1]+b1);
            *reinterpret_cast<float2*>(sX1 + q1 * LDX1 + oc) = make_float2(acc[s*4+2]+b0, acc[s*4+3]+b1);
        }
    }
    __syncthreads();

    // =========== scatter store, front-batched: quary1 preloaded (MLP 11), then pure stores ===========
    {
        float qv[11];
#pragma unroll
        for (int k = 0; k < 11; k++) {
            int idx = tid + k * THREADS;
            if (idx < 64 * 121) {
                int p = idx / 121, c = idx - p * 121;
                qv[k] = (c < 120) ? quary1[(size_t)(wi * 64 + p) * 120 + c] : 0.f;
            }
        }
#pragma unroll
        for (int k = 0; k < 11; k++) {
            int idx = tid + k * THREADS;
            if (idx < 64 * 121) {
                int p = idx / 121, c = idx - p * 121;
                int rowg = (wy * 8 + (p >> 3) + 4) & 255;
                int colg = (wx * 8 + (p & 7) + 4) & 255;
                float pv = sPred[p];
                float v;
                if (c == 120) v = pv;
                else v = (pv != 0.f) ? sX1[p * LDX1 + c] : qv[k];
                out[(size_t)(rowg * 256 + colg) * 121 + c] = v;
            }
        }
    }
}

// ---------------- launch ----------------
extern "C" void kernel_launch(void* const* d_in, const int* in_sizes, int n_in,
                              void* d_out, int out_size)
{
    (void)in_sizes; (void)n_in; (void)out_size;
    const float* x        = (const float*)d_in[0];
    const float* quary0   = (const float*)d_in[1];
    const float* quary1   = (const float*)d_in[2];
    const float* qkv_w    = (const float*)d_in[3];
    const float* qkv_b    = (const float*)d_in[4];
    const float* proj_w   = (const float*)d_in[5];
    const float* proj_b   = (const float*)d_in[6];
    const float* rpb_tab  = (const float*)d_in[7];
    const float* pm_w     = (const float*)d_in[8];
    const float* pm_b     = (const float*)d_in[9];
    // d_in[10] = attn_mask : intentionally unused (recomputed analytically)
    const int*   rel_idx  = (const int*)d_in[11];
    float* out = (float*)d_out;

    cudaFuncSetAttribute(swin_main_kernel, cudaFuncAttributeMaxDynamicSharedMemorySize, SMEM_TOTAL);

    prep_kernel<<<128, 256>>>(qkv_w, qkv_b, proj_w, rpb_tab, rel_idx);
    swin_main_kernel<<<1024, THREADS, SMEM_TOTAL>>>(x, quary0, quary1, proj_b, pm_w, pm_b, out);
}

// round 17
// speedup vs baseline: 1.7230x; 1.0025x over previous
#include <cuda_runtime.h>
#include <cuda_bf16.h>
#include <cstdint>

#define DEV __device__ __forceinline__

static constexpr int   THREADS = 768;   // 24 warps
static constexpr float SCALE_Q = 0.223606797749978969f;   // 20^-0.5
static constexpr float LOG2E   = 1.4426950408889634f;
static constexpr float MASKC   = 144.26950408889634f;     // 100 * log2(e)

// ---------------- shared memory layout (bytes) ----------------
static constexpr int LDA  = 136;   // elems; 272B rows -> conflict-free LDSM
static constexpr int LDX1 = 124;

static constexpr int OFF_X    = 0;                  // sX bf16[192][136] (52224) | later proj W
static constexpr int OFF_WQ   = 52224;              // Wq (32640) | later sV bf16[6][192][24] (55296, spans WQ+WK) | sX1 f32[64][124]
static constexpr int OFF_WK   = 84864;              // Wk (32640)
static constexpr int OFF_WV   = 117504;             // Wv (32640) | later sO bf16[64][136] (16896)
static constexpr int OFF_K    = 150144;             // sK bf16[6][192][24] (55296)
static constexpr int OFF_Q    = 205440;             // sQ bf16[6][64][24] (18432)
static constexpr int OFF_PRED = 223872;             // f32[64]
static constexpr int OFF_RID  = 224128;             // int[64]
static constexpr int SMEM_TOTAL = 224384;

// ---------------- preprocessed device globals ----------------
__device__ __align__(16) __nv_bfloat16 g_wqkv[360 * 128];     // qkv_w padded; q rows pre-scaled by SCALE_Q*log2e
__device__ __align__(16) __nv_bfloat16 g_projw[120 * 128];    // proj_w padded
__device__ __align__(16) float         g_bqkv[360];           // qkv bias; q part pre-scaled by SCALE_Q*log2e
__device__ __align__(16) __nv_bfloat16 g_rpb[6 * 64 * 192];   // gathered rel-pos bias [h][q][k], pre-scaled by log2e

__global__ void prep_kernel(const float* __restrict__ qkv_w, const float* __restrict__ qkv_b,
                            const float* __restrict__ proj_w, const float* __restrict__ rpb_table,
                            const int* __restrict__ rel_idx)
{
    const int i0 = blockIdx.x * blockDim.x + threadIdx.x;
    const int st = gridDim.x * blockDim.x;
    for (int t = i0; t < 360 * 128; t += st) {
        int r = t >> 7, c = t & 127;
        float v = (c < 120) ? qkv_w[r * 120 + c] : 0.f;
        if (r < 120) v *= SCALE_Q * LOG2E;
        g_wqkv[t] = __float2bfloat16(v);
    }
    for (int t = i0; t < 120 * 128; t += st) {
        int r = t >> 7, c = t & 127;
        g_projw[t] = __float2bfloat16((c < 120) ? proj_w[r * 120 + c] : 0.f);
    }
    for (int t = i0; t < 360; t += st)
        g_bqkv[t] = qkv_b[t] * ((t < 120) ? SCALE_Q * LOG2E : 1.f);
    for (int t = i0; t < 6 * 64 * 192; t += st) {
        int h = t / 12288, rem = t % 12288;          // rem = q*192 + k  (rel_idx flat order)
        g_rpb[t] = __float2bfloat16(rpb_table[rel_idx[rem] * 6 + h] * LOG2E);
    }
}

// ---------------- mma / ldmatrix helpers ----------------
DEV uint32_t s2u(const void* p) { return (uint32_t)__cvta_generic_to_shared(p); }

DEV void ldsm4(uint32_t* r, uint32_t a) {
    asm volatile("ldmatrix.sync.aligned.m8n8.x4.shared.b16 {%0,%1,%2,%3}, [%4];"
                 : "=r"(r[0]), "=r"(r[1]), "=r"(r[2]), "=r"(r[3]) : "r"(a));
}
DEV void ldsm2(uint32_t* r, uint32_t a) {
    asm volatile("ldmatrix.sync.aligned.m8n8.x2.shared.b16 {%0,%1}, [%2];"
                 : "=r"(r[0]), "=r"(r[1]) : "r"(a));
}
DEV void ldsm4t(uint32_t* r, uint32_t a) {
    asm volatile("ldmatrix.sync.aligned.m8n8.x4.trans.shared.b16 {%0,%1,%2,%3}, [%4];"
                 : "=r"(r[0]), "=r"(r[1]), "=r"(r[2]), "=r"(r[3]) : "r"(a));
}
DEV void ldsm2t(uint32_t* r, uint32_t a) {
    asm volatile("ldmatrix.sync.aligned.m8n8.x2.trans.shared.b16 {%0,%1}, [%2];"
                 : "=r"(r[0]), "=r"(r[1]) : "r"(a));
}

DEV uint32_t packbf(float a, float b) {
    __nv_bfloat162 t = __floats2bfloat162_rn(a, b);
    return *reinterpret_cast<uint32_t*>(&t);
}

DEV float ex2(float x) {
    float y;
    asm("ex2.approx.f32 %0, %1;" : "=f"(y) : "f"(x));
    return y;
}

DEV void mma16816(float* c, uint32_t a0, uint32_t a1, uint32_t a2, uint32_t a3,
                  uint32_t b0, uint32_t b1) {
    asm volatile("mma.sync.aligned.m16n8k16.row.col.f32.bf16.bf16.f32 "
                 "{%0,%1,%2,%3}, {%4,%5,%6,%7}, {%8,%9}, {%0,%1,%2,%3};\n"
                 : "+f"(c[0]), "+f"(c[1]), "+f"(c[2]), "+f"(c[3])
                 : "r"(a0), "r"(a1), "r"(a2), "r"(a3), "r"(b0), "r"(b1));
}

DEV void mma1688(float* c, uint32_t a0, uint32_t a1, uint32_t b0) {
    asm volatile("mma.sync.aligned.m16n8k8.row.col.f32.bf16.bf16.f32 "
                 "{%0,%1,%2,%3}, {%4,%5}, {%6}, {%0,%1,%2,%3};\n"
                 : "+f"(c[0]), "+f"(c[1]), "+f"(c[2]), "+f"(c[3])
                 : "r"(a0), "r"(a1), "r"(b0));
}

// 16(M) x 40(N) x 128(K): A row-major [.,LDA], B n-major [n][k] stride LDA. LDSM-fed.
DEV void gemm16x40(const __nv_bfloat16* __restrict__ A, const __nv_bfloat16* __restrict__ B,
                   float* acc, int lane)
{
    const int r16 = lane & 15, k8 = (lane >> 4) * 8;
    uint32_t aA  = s2u(A + r16 * LDA + k8);
    uint32_t aB0 = s2u(B + r16 * LDA + k8);
    uint32_t aB1 = s2u(B + (16 + r16) * LDA + k8);
    uint32_t aB2 = s2u(B + (32 + (lane & 7)) * LDA + ((lane >> 3) & 1) * 8);
#pragma unroll
    for (int ks = 0; ks < 8; ks++) {
        uint32_t av[4], b0[4], b1[4], b2[2];
        ldsm4(av, aA); ldsm4(b0, aB0); ldsm4(b1, aB1); ldsm2(b2, aB2);
        aA += 32; aB0 += 32; aB1 += 32; aB2 += 32;
        mma16816(acc + 0,  av[0], av[1], av[2], av[3], b0[0], b0[2]);
        mma16816(acc + 4,  av[0], av[1], av[2], av[3], b0[1], b0[3]);
        mma16816(acc + 8,  av[0], av[1], av[2], av[3], b1[0], b1[2]);
        mma16816(acc + 12, av[0], av[1], av[2], av[3], b1[1], b1[3]);
        mma16816(acc + 16, av[0], av[1], av[2], av[3], b2[0], b2[1]);
    }
}

// 32(M) x 40(N) x 128(K). acc[s*8+0..3] = rows 0-15 of tile s, +4..7 = rows 16-31.
DEV void gemm32x40(const __nv_bfloat16* __restrict__ A, const __nv_bfloat16* __restrict__ B,
                   float* acc, int lane)
{
    const int r16 = lane & 15, k8 = (lane >> 4) * 8;
    uint32_t aA0 = s2u(A + r16 * LDA + k8);
    uint32_t aA1 = s2u(A + (16 + r16) * LDA + k8);
    uint32_t aB0 = s2u(B + r16 * LDA + k8);
    uint32_t aB1 = s2u(B + (16 + r16) * LDA + k8);
    uint32_t aB2 = s2u(B + (32 + (lane & 7)) * LDA + ((lane >> 3) & 1) * 8);
#pragma unroll
    for (int ks = 0; ks < 8; ks++) {
        uint32_t av0[4], av1[4], b0[4], b1[4], b2[2];
        ldsm4(av0, aA0); ldsm4(av1, aA1); ldsm4(b0, aB0); ldsm4(b1, aB1); ldsm2(b2, aB2);
        aA0 += 32; aA1 += 32; aB0 += 32; aB1 += 32; aB2 += 32;
        mma16816(acc + 0,  av0[0], av0[1], av0[2], av0[3], b0[0], b0[2]);
        mma16816(acc + 4,  av1[0], av1[1], av1[2], av1[3], b0[0], b0[2]);
        mma16816(acc + 8,  av0[0], av0[1], av0[2], av0[3], b0[1], b0[3]);
        mma16816(acc + 12, av1[0], av1[1], av1[2], av1[3], b0[1], b0[3]);
        mma16816(acc + 16, av0[0], av0[1], av0[2], av0[3], b1[0], b1[2]);
        mma16816(acc + 20, av1[0], av1[1], av1[2], av1[3], b1[0], b1[2]);
        mma16816(acc + 24, av0[0], av0[1], av0[2], av0[3], b1[1], b1[3]);
        mma16816(acc + 28, av1[0], av1[1], av1[2], av1[3], b1[1], b1[3]);
        mma16816(acc + 32, av0[0], av0[1], av0[2], av0[3], b2[0], b2[1]);
        mma16816(acc + 36, av1[0], av1[1], av1[2], av1[3], b2[0], b2[1]);
    }
}

DEV void stage_w(const __nv_bfloat16* __restrict__ gsrc, __nv_bfloat16* __restrict__ sdst, int tid) {
#pragma unroll
    for (int k = 0; k < 3; k++) {
        int i = tid + k * THREADS;
        if (i < 120 * 16) {
            int r = i >> 4, c = i & 15;
            *reinterpret_cast<uint4*>(sdst + r * LDA + c * 8) =
                *reinterpret_cast<const uint4*>(gsrc + r * 128 + c * 8);
        }
    }
}

// ---------------- main fused kernel: one CTA per window ----------------
__global__ void __launch_bounds__(THREADS, 1)
swin_main_kernel(const float* __restrict__ x, const float* __restrict__ quary0,
                 const float* __restrict__ quary1, const float* __restrict__ proj_b,
                 const float* __restrict__ pm_w, const float* __restrict__ pm_b,
                 float* __restrict__ out)
{
    extern __shared__ char smem[];
    __nv_bfloat16* sX   = (__nv_bfloat16*)(smem + OFF_X);
    __nv_bfloat16* sWp  = (__nv_bfloat16*)(smem + OFF_X);    // proj W (after G2)
    __nv_bfloat16* sWq  = (__nv_bfloat16*)(smem + OFF_WQ);
    __nv_bfloat16* sV   = (__nv_bfloat16*)(smem + OFF_WQ);   // V [6][192][24] (after G1, spans WQ+WK)
    float*         sX1  = (float*)(smem + OFF_WQ);           // proj out (after attention)
    __nv_bfloat16* sWk  = (__nv_bfloat16*)(smem + OFF_WK);
    __nv_bfloat16* sWv  = (__nv_bfloat16*)(smem + OFF_WV);
    __nv_bfloat16* sO   = (__nv_bfloat16*)(smem + OFF_WV);   // attention out (after G2)
    __nv_bfloat16* sK   = (__nv_bfloat16*)(smem + OFF_K);
    __nv_bfloat16* sQ   = (__nv_bfloat16*)(smem + OFF_Q);
    float*         sPred= (float*)(smem + OFF_PRED);
    int*           sRid = (int*)(smem + OFF_RID);

    const int tid  = threadIdx.x;
    const int lane = tid & 31;
    const int warp = tid >> 5;          // 0..23
    const int grp  = lane >> 2;         // 0..7
    const int tg   = lane & 3;          // 0..3
    const int wi   = blockIdx.x;
    const int wy   = wi >> 5, wx = wi & 31;
    const bool maskw = (wy == 31) || (wx == 31);
    const __nv_bfloat16 bz = __float2bfloat16(0.f);

    // =========== Phase A: X load (front-batched), pads, rids, Wq+Wk+Wv stage, pred ===========
    {
        float4 t[8];
#pragma unroll
        for (int k = 0; k < 8; k++) {
            int i = tid + k * THREADS;
            if (i < 192 * 30) {
                int n = i / 30, v = i - n * 30;
                int f = n >> 6, p = n & 63;
                int rowg = (wy * 8 + (p >> 3) + 4) & 255;
                int colg = (wx * 8 + (p & 7) + 4) & 255;
                t[k] = *reinterpret_cast<const float4*>(
                    x + ((size_t)((f * 256 + rowg) * 256 + colg)) * 120 + v * 4);
            }
        }
#pragma unroll
        for (int k = 0; k < 8; k++) {
            int i = tid + k * THREADS;
            if (i < 192 * 30) {
                int n = i / 30, v = i - n * 30;
                uint32_t* dst = reinterpret_cast<uint32_t*>(sX + n * LDA + v * 4);
                dst[0] = packbf(t[k].x, t[k].y);
                dst[1] = packbf(t[k].z, t[k].w);
            }
        }
    }
    for (int i = tid; i < 192 * 8; i += THREADS) sX[(i >> 3) * LDA + 120 + (i & 7)] = bz;
    for (int i = tid; i < 6 * 64 * 4; i += THREADS) {
        int h = i >> 8, r = (i >> 2) & 63, c = 20 + (i & 3);
        sQ[(h * 64 + r) * 24 + c] = bz;
    }
    for (int i = tid; i < 6 * 192 * 4; i += THREADS) {
        int h = i / 768, r = (i >> 2) % 192, c = 20 + (i & 3);
        sK[(h * 192 + r) * 24 + c] = bz;
    }
    if (tid < 64) {
        int r = tid >> 3, c = tid & 7;
        int rz = (wy == 31) ? ((r < 4) ? 1 : 2) : 0;
        int cz = (wx == 31) ? ((c < 4) ? 1 : 2) : 0;
        sRid[tid] = rz * 3 + cz;
    }
    stage_w(g_wqkv,             sWq, tid);   // Wq (pre-scaled incl. log2e)
    stage_w(g_wqkv + 120 * 128, sWk, tid);   // Wk
    stage_w(g_wqkv + 240 * 128, sWv, tid);   // Wv (prefetched here; used in G2)

    // pred (pure fp32 from global x): 24 warps x 3 queries, fully unrolled so LDGs hoist
    {
        const float pmb = pm_b[0];
#pragma unroll
        for (int it = 0; it < 3; it++) {
            int q = it * 24 + warp;
            float s = 0.f;
            if (q < 64) {
                int rowg = (wy * 8 + (q >> 3) + 4) & 255;
                int colg = (wx * 8 + (q & 7) + 4) & 255;
                const float* xr = x + ((size_t)((2 * 256 + rowg) * 256 + colg)) * 120;
                const float* qr = quary0 + (size_t)(wi * 64 + q) * 120;
#pragma unroll
                for (int k = 0; k < 4; k++) {
                    int ch = lane + k * 32;
                    if (ch < 120) s += fabsf(xr[ch] - qr[ch]) * pm_w[ch];
                }
            }
#pragma unroll
            for (int off = 16; off; off >>= 1) s += __shfl_xor_sync(0xffffffffu, s, off);
            if (q < 64 && lane == 0) sPred[q] = (s + pmb >= 0.f) ? 1.f : 0.f;
        }
    }
    __syncthreads();

    // =========== G1: K GEMM (warps 0..17, 32x40) + Q GEMM (warps 18..23, 32x40) ===========
    if (warp < 18) {
        const int r = warp / 3, nt = warp % 3;
        float acc[40];
#pragma unroll
        for (int i = 0; i < 40; i++) acc[i] = 0.f;
        gemm32x40(sX + r * 32 * LDA, sWk + (nt * 40) * LDA, acc, lane);
        const int t0 = r * 32 + grp;
#pragma unroll
        for (int s = 0; s < 5; s++) {
            int oc = nt * 40 + s * 8 + tg * 2;
            int hh = oc / 20, d = oc % 20;
            float b0 = g_bqkv[120 + oc], b1 = g_bqkv[121 + oc];
            __nv_bfloat16* base = sK + (hh * 192) * 24 + d;
            *reinterpret_cast<uint32_t*>(base + (t0     ) * 24) = packbf(acc[s*8+0]+b0, acc[s*8+1]+b1);
            *reinterpret_cast<uint32_t*>(base + (t0 +  8) * 24) = packbf(acc[s*8+2]+b0, acc[s*8+3]+b1);
            *reinterpret_cast<uint32_t*>(base + (t0 + 16) * 24) = packbf(acc[s*8+4]+b0, acc[s*8+5]+b1);
            *reinterpret_cast<uint32_t*>(base + (t0 + 24) * 24) = packbf(acc[s*8+6]+b0, acc[s*8+7]+b1);
        }
    } else {
        const int t = warp - 18;                  // 0..5
        const int mblk = t / 3, nt = t % 3;       // mblk: 0..1 (rows 128-159 / 160-191)
        float acc[40];
#pragma unroll
        for (int i = 0; i < 40; i++) acc[i] = 0.f;
        gemm32x40(sX + (128 + mblk * 32) * LDA, sWq + (nt * 40) * LDA, acc, lane);
        const int q0 = mblk * 32 + grp;
#pragma unroll
        for (int s = 0; s < 5; s++) {
            int oc = nt * 40 + s * 8 + tg * 2;
            int hh = oc / 20, d = oc % 20;
            float b0 = g_bqkv[oc], b1 = g_bqkv[oc + 1];
            __nv_bfloat16* base = sQ + (hh * 64) * 24 + d;
            *reinterpret_cast<uint32_t*>(base + (q0     ) * 24) = packbf(acc[s*8+0]+b0, acc[s*8+1]+b1);
            *reinterpret_cast<uint32_t*>(base + (q0 +  8) * 24) = packbf(acc[s*8+2]+b0, acc[s*8+3]+b1);
            *reinterpret_cast<uint32_t*>(base + (q0 + 16) * 24) = packbf(acc[s*8+4]+b0, acc[s*8+5]+b1);
            *reinterpret_cast<uint32_t*>(base + (q0 + 24) * 24) = packbf(acc[s*8+6]+b0, acc[s*8+7]+b1);
        }
    }
    __syncthreads();

    // =========== G2: V GEMM (warps 0..17) K-style into sV + pads/ones by warps 18..23 ===========
    if (warp < 18) {
        const int r = warp / 3, nt = warp % 3;
        float acc[40];
#pragma unroll
        for (int i = 0; i < 40; i++) acc[i] = 0.f;
        gemm32x40(sX + r * 32 * LDA, sWv + (nt * 40) * LDA, acc, lane);
        const int t0 = r * 32 + grp;
#pragma unroll
        for (int s = 0; s < 5; s++) {
            int oc = nt * 40 + s * 8 + tg * 2;
            int hh = oc / 20, d = oc % 20;
            float b0 = g_bqkv[240 + oc], b1 = g_bqkv[241 + oc];
            __nv_bfloat16* base = sV + (hh * 192) * 24 + d;
            *reinterpret_cast<uint32_t*>(base + (t0     ) * 24) = packbf(acc[s*8+0]+b0, acc[s*8+1]+b1);
            *reinterpret_cast<uint32_t*>(base + (t0 +  8) * 24) = packbf(acc[s*8+2]+b0, acc[s*8+3]+b1);
            *reinterpret_cast<uint32_t*>(base + (t0 + 16) * 24) = packbf(acc[s*8+4]+b0, acc[s*8+5]+b1);
            *reinterpret_cast<uint32_t*>(base + (t0 + 24) * 24) = packbf(acc[s*8+6]+b0, acc[s*8+7]+b1);
        }
    } else {
        // sV pad fill: d20 = 1.0 (ones column -> row sums via PV), d21..23 = 0
        const int tid2 = (warp - 18) * 32 + lane;   // 0..191
        const uint2 pv = make_uint2(0x3F80u, 0u);   // bf16 {1.0, 0}, {0, 0}
        for (int i = tid2; i < 6 * 192; i += 192)
            *reinterpret_cast<uint2*>(sV + i * 24 + 20) = pv;
    }
    __syncthreads();

    // sX dead: stage proj W (LDG hides under attention); zero sO pads
    stage_w(g_projw, sWp, tid);
    for (int i = tid; i < 64 * 16; i += THREADS) sO[(i >> 4) * LDA + 120 + (i & 15)] = bz;

    // =========== attention: 24 warp-tasks, 4x48 key chunks, no-max softmax (log2 domain) ===========
    {
        const int h    = warp >> 2;          // 0..5
        const int mblk = warp & 3;           // 0..3
        const int q0   = mblk * 16 + grp;
        const int q1   = q0 + 8;

        uint32_t aq[6];
        {
            const __nv_bfloat16* Qb = sQ + (h * 64 + mblk * 16) * 24;
            ldsm4(aq,     s2u(Qb + (lane & 15) * 24 + (lane >> 4) * 8));
            ldsm2(aq + 4, s2u(Qb + (lane & 15) * 24 + 16));
        }

        float O[12];
#pragma unroll
        for (int i = 0; i < 12; i++) O[i] = 0.f;
        const int rq0 = sRid[q0], rq1 = sRid[q1];
        // trans-LDSM lane->token mapping for PV B operand
        const int tl = ((lane & 8) ? 8 : 0) + (lane & 7);

#pragma unroll 1
        for (int c = 0; c < 4; c++) {
            uint32_t ru0[6], ru1[6];
            {
                const uint32_t* rp0 = reinterpret_cast<const uint32_t*>(g_rpb + (h * 64 + q0) * 192 + c * 48) + tg;
                const uint32_t* rp1 = reinterpret_cast<const uint32_t*>(g_rpb + (h * 64 + q1) * 192 + c * 48) + tg;
#pragma unroll
                for (int j = 0; j < 6; j++) { ru0[j] = rp0[j * 4]; ru1[j] = rp1[j * 4]; }
            }

            float s[24];
#pragma unroll
            for (int i = 0; i < 24; i++) s[i] = 0.f;

            const __nv_bfloat16* Kh = sK + (h * 192 + c * 48) * 24;
            {
                uint32_t bp = s2u(Kh + (lane & 15) * 24 + (lane >> 4) * 8);
#pragma unroll
                for (int p = 0; p < 3; p++) {
                    uint32_t kb[4];
                    ldsm4(kb, bp + p * 768);          // 16 tokens * 48B
                    mma16816(s + (2*p  ) * 4, aq[0], aq[1], aq[2], aq[3], kb[0], kb[2]);
                    mma16816(s + (2*p+1) * 4, aq[0], aq[1], aq[2], aq[3], kb[1], kb[3]);
                }
                uint32_t kt[6];
                ldsm4(kt,     s2u(Kh + lane * 24 + 16));
                ldsm2(kt + 4, s2u(Kh + (32 + (lane & 15)) * 24 + 16));
#pragma unroll
                for (int j = 0; j < 6; j++) mma1688(s + j * 4, aq[4], aq[5], kt[j]);
            }

#pragma unroll
            for (int j = 0; j < 6; j++) {
                float2 f0 = __bfloat1622float2(*reinterpret_cast<__nv_bfloat162*>(&ru0[j]));
                float2 f1 = __bfloat1622float2(*reinterpret_cast<__nv_bfloat162*>(&ru1[j]));
                s[j*4+0] += f0.x; s[j*4+1] += f0.y;
                s[j*4+2] += f1.x; s[j*4+3] += f1.y;
            }

            if (maskw) {
#pragma unroll
                for (int j = 0; j < 6; j++) {
                    int kc = (c * 48 + j * 8 + tg * 2) & 63;
                    int rk0 = sRid[kc], rk1 = sRid[kc + 1];
                    if (rk0 != rq0) s[j*4+0] -= MASKC;
                    if (rk1 != rq0) s[j*4+1] -= MASKC;
                    if (rk0 != rq1) s[j*4+2] -= MASKC;
                    if (rk1 != rq1) s[j*4+3] -= MASKC;
                }
            }

#pragma unroll
            for (int i = 0; i < 24; i++) s[i] = ex2(s[i]);

            // PV: B from K-major sV via ldmatrix.trans
            const __nv_bfloat16* Vh = sV + (h * 192 + c * 48) * 24;
            uint32_t pv4 = s2u(Vh + tl * 24 + ((lane & 16) ? 8 : 0));   // m0/m1: d0-7, m2/m3: d8-15
            uint32_t pv2 = s2u(Vh + tl * 24 + 16);                      // d16-23
#pragma unroll
            for (int kk = 0; kk < 3; kk++) {
                uint32_t vb[4], vt[2];
                ldsm4t(vb, pv4 + kk * 768);
                ldsm2t(vt, pv2 + kk * 768);
                uint32_t a0 = packbf(s[kk*8+0], s[kk*8+1]);
                uint32_t a1 = packbf(s[kk*8+2], s[kk*8+3]);
                uint32_t a2 = packbf(s[kk*8+4], s[kk*8+5]);
                uint32_t a3 = packbf(s[kk*8+6], s[kk*8+7]);
                mma16816(O + 0, a0, a1, a2, a3, vb[0], vb[1]);
                mma16816(O + 4, a0, a1, a2, a3, vb[2], vb[3]);
                mma16816(O + 8, a0, a1, a2, a3, vt[0], vt[1]);
            }
        }

        // row sums live in col 20 = O[8] (q0) / O[10] (q1) of lanes with tg==2
        const int src = (lane & ~3) | 2;
        const float inv0 = 1.f / __shfl_sync(0xffffffffu, O[8],  src);
        const float inv1 = 1.f / __shfl_sync(0xffffffffu, O[10], src);
#pragma unroll
        for (int nt = 0; nt < 3; nt++) {
            int d = nt * 8 + tg * 2;
            if (d < 20) {
                *reinterpret_cast<uint32_t*>(sO + q0 * LDA + h * 20 + d) = packbf(O[nt*4+0]*inv0, O[nt*4+1]*inv0);
                *reinterpret_cast<uint32_t*>(sO + q1 * LDA + h * 20 + d) = packbf(O[nt*4+2]*inv1, O[nt*4+3]*inv1);
            }
        }
    }
    __syncthreads();

    // =========== proj GEMM + blend (proj W staged in sWp during attention) ===========
    if (warp < 12) {
        const int mt = warp & 3, nt = warp >> 2;
        const int q0 = mt * 16 + grp, q1 = q0 + 8;
        float acc[20];
#pragma unroll
        for (int i = 0; i < 20; i++) acc[i] = 0.f;
        gemm16x40(sO + mt * 16 * LDA, sWp + (nt * 40) * LDA, acc, lane);
#pragma unroll
        for (int s = 0; s < 5; s++) {
            int oc = nt * 40 + s * 8 + tg * 2;
            float b0 = proj_b[oc], b1 = proj_b[oc + 1];
            *reinterpret_cast<float2*>(sX1 + q0 * LDX1 + oc) = make_float2(acc[s*4+0]+b0, acc[s*4+1]+b1);
            *reinterpret_cast<float2*>(sX1 + q1 * LDX1 + oc) = make_float2(acc[s*4+2]+b0, acc[s*4+3]+b1);
        }
    }
    __syncthreads();

    // =========== scatter store, front-batched: quary1 preloaded (MLP 11), then pure stores ===========
    {
        float qv[11];
#pragma unroll
        for (int k = 0; k < 11; k++) {
            int idx = tid + k * THREADS;
            if (idx < 64 * 121) {
                int p = idx / 121, c = idx - p * 121;
                qv[k] = (c < 120) ? quary1[(size_t)(wi * 64 + p) * 120 + c] : 0.f;
            }
        }
#pragma unroll
        for (int k = 0; k < 11; k++) {
            int idx = tid + k * THREADS;
            if (idx < 64 * 121) {
                int p = idx / 121, c = idx - p * 121;
                int rowg = (wy * 8 + (p >> 3) + 4) & 255;
                int colg = (wx * 8 + (p & 7) + 4) & 255;
                float pv = sPred[p];
                float v;
                if (c == 120) v = pv;
                else v = (pv != 0.f) ? sX1[p * LDX1 + c] : qv[k];
                out[(size_t)(rowg * 256 + colg) * 121 + c] = v;
            }
        }
    }
}

// ---------------- launch ----------------
extern "C" void kernel_launch(void* const* d_in, const int* in_sizes, int n_in,
                              void* d_out, int out_size)
{
    (void)in_sizes; (void)n_in; (void)out_size;
    const float* x        = (const float*)d_in[0];
    const float* quary0   = (const float*)d_in[1];
    const float* quary1   = (const float*)d_in[2];
    const float* qkv_w    = (const float*)d_in[3];
    const float* qkv_b    = (const float*)d_in[4];
    const float* proj_w   = (const float*)d_in[5];
    const float* proj_b   = (const float*)d_in[6];
    const float* rpb_tab  = (const float*)d_in[7];
    const float* pm_w     = (const float*)d_in[8];
    const float* pm_b     = (const float*)d_in[9];
    // d_in[10] = attn_mask : intentionally unused (recomputed analytically)
    const int*   rel_idx  = (const int*)d_in[11];
    float* out = (float*)d_out;

    cudaFuncSetAttribute(swin_main_kernel, cudaFuncAttributeMaxDynamicSharedMemorySize, SMEM_TOTAL);

    prep_kernel<<<128, 256>>>(qkv_w, qkv_b, proj_w, rpb_tab, rel_idx);
    swin_main_kernel<<<1024, THREADS, SMEM_TOTAL>>>(x, quary0, quary1, proj_b, pm_w, pm_b, out);
}